// round 8
// baseline (speedup 1.0000x reference)
#include <cuda_runtime.h>
#include <cuda_bf16.h>
#include <math.h>
#include <stdint.h>

#define CC     512
#define T_LEN  2048
#define BATCH  4
#define NH     8
#define HD     64

#define PW_ELEMS (CC * CC)
#define X_ELEMS ((size_t)BATCH * CC * T_LEN)
#define QKV_ELEMS ((size_t)BATCH * 3 * CC * T_LEN)
#define QW_ELEMS (3 * CC * CC)

__device__ int           g_imax[2];                 // 0: qkv_w, 1: x
__device__ int8_t        g_w8h[QW_ELEMS], g_w8l[QW_ELEMS];
__device__ int8_t        g_x8h[X_ELEMS],  g_x8l[X_ELEMS];    // x^T [b][t][c]
__device__ __nv_bfloat16 g_whi[PW_ELEMS], g_wlo[PW_ELEMS];   // proj_w split
__device__ __nv_bfloat16 g_xhi[X_ELEMS],  g_xlo[X_ELEMS];    // attn out split
__device__ __nv_bfloat16 g_qkvhi[QKV_ELEMS], g_qkvlo[QKV_ELEMS];

// ===================== helpers =====================
__device__ __forceinline__ uint32_t smem_u32(const void* p) {
    uint32_t a;
    asm("{ .reg .u64 t; cvta.to.shared.u64 t, %1; cvt.u32.u64 %0, t; }" : "=r"(a) : "l"(p));
    return a;
}
__device__ __forceinline__ uint32_t pk_bf2(__nv_bfloat16 a, __nv_bfloat16 b) {
    __nv_bfloat162 t(a, b);
    return *reinterpret_cast<uint32_t*>(&t);
}
__device__ __forceinline__ void split2(float x, float y, uint32_t& hi, uint32_t& lo) {
    __nv_bfloat16 xh = __float2bfloat16(x), yh = __float2bfloat16(y);
    __nv_bfloat16 xl = __float2bfloat16(x - __bfloat162float(xh));
    __nv_bfloat16 yl = __float2bfloat16(y - __bfloat162float(yh));
    hi = pk_bf2(xh, yh);
    lo = pk_bf2(xl, yl);
}
__device__ __forceinline__ void ldsm4(uint32_t& r0, uint32_t& r1, uint32_t& r2, uint32_t& r3,
                                      uint32_t addr) {
    asm volatile("ldmatrix.sync.aligned.m8n8.x4.shared.b16 {%0,%1,%2,%3}, [%4];"
                 : "=r"(r0), "=r"(r1), "=r"(r2), "=r"(r3) : "r"(addr));
}
__device__ __forceinline__ void ldsm4t(uint32_t& r0, uint32_t& r1, uint32_t& r2, uint32_t& r3,
                                       uint32_t addr) {
    asm volatile("ldmatrix.sync.aligned.m8n8.x4.trans.shared.b16 {%0,%1,%2,%3}, [%4];"
                 : "=r"(r0), "=r"(r1), "=r"(r2), "=r"(r3) : "r"(addr));
}
__device__ __forceinline__ void mma16816(float* c, uint32_t a0, uint32_t a1, uint32_t a2,
                                         uint32_t a3, uint32_t b0, uint32_t b1) {
    asm volatile(
        "mma.sync.aligned.m16n8k16.row.col.f32.bf16.bf16.f32 "
        "{%0,%1,%2,%3}, {%4,%5,%6,%7}, {%8,%9}, {%0,%1,%2,%3};"
        : "+f"(c[0]), "+f"(c[1]), "+f"(c[2]), "+f"(c[3])
        : "r"(a0), "r"(a1), "r"(a2), "r"(a3), "r"(b0), "r"(b1));
}
__device__ __forceinline__ void imma16832(int* c, uint32_t a0, uint32_t a1, uint32_t a2,
                                          uint32_t a3, uint32_t b0, uint32_t b1) {
    asm volatile(
        "mma.sync.aligned.m16n8k32.row.col.s32.s8.s8.s32 "
        "{%0,%1,%2,%3}, {%4,%5,%6,%7}, {%8,%9}, {%0,%1,%2,%3};"
        : "+r"(c[0]), "+r"(c[1]), "+r"(c[2]), "+r"(c[3])
        : "r"(a0), "r"(a1), "r"(a2), "r"(a3), "r"(b0), "r"(b1));
}
__device__ __forceinline__ void cp16(uint32_t dst, const void* src) {
    asm volatile("cp.async.cg.shared.global [%0], [%1], 16;" :: "r"(dst), "l"(src));
}
#define CP_COMMIT() asm volatile("cp.async.commit_group;" ::: "memory")
#define CP_WAIT0()  asm volatile("cp.async.wait_group 0;" ::: "memory")

__device__ __forceinline__ void quant15(float v, float inv, int& ah, int& al) {
    int q = __float2int_rn(v * inv);
    q = max(-16256, min(16256, q));
    ah = __float2int_rn((float)q * (1.f / 128.f));
    al = q - (ah << 7);
}

// ===================== prep kernels =====================
__global__ void init_scales() { if (threadIdx.x < 2) g_imax[threadIdx.x] = 0; }

__global__ void __launch_bounds__(256) maxabs_f32(const float4* __restrict__ src, int n4, int slot)
{
    float m = 0.f;
    for (int i = blockIdx.x * 256 + threadIdx.x; i < n4; i += gridDim.x * 256) {
        float4 v = src[i];
        m = fmaxf(m, fmaxf(fmaxf(fabsf(v.x), fabsf(v.y)), fmaxf(fabsf(v.z), fabsf(v.w))));
    }
#pragma unroll
    for (int o = 16; o > 0; o >>= 1) m = fmaxf(m, __shfl_xor_sync(0xffffffffu, m, o));
    __shared__ float red[8];
    if ((threadIdx.x & 31) == 0) red[threadIdx.x >> 5] = m;
    __syncthreads();
    if (threadIdx.x == 0) {
        float r = red[0];
#pragma unroll
        for (int i = 1; i < 8; ++i) r = fmaxf(r, red[i]);
        atomicMax(&g_imax[slot], __float_as_int(r));
    }
}

__global__ void __launch_bounds__(256) quant_w(const float* __restrict__ src, int n)
{
    int i = blockIdx.x * 256 + threadIdx.x;
    if (i >= n) return;
    float inv = 16256.f / __int_as_float(g_imax[0]);
    int ah, al;
    quant15(src[i], inv, ah, al);
    g_w8h[i] = (int8_t)ah;
    g_w8l[i] = (int8_t)al;
}

// x [b][C][T] -> x^T [b][T][C] int8 limbs
__global__ void quant_xT(const float* __restrict__ x)
{
    __shared__ float tile[32][33];
    const int t0 = blockIdx.x * 32, c0 = blockIdx.y * 32, z = blockIdx.z;
    const int tx = threadIdx.x, ty = threadIdx.y;
    const float* xz = x + (size_t)z * CC * T_LEN;
#pragma unroll
    for (int k = 0; k < 4; ++k)
        tile[ty + 8 * k][tx] = xz[(size_t)(c0 + ty + 8 * k) * T_LEN + t0 + tx];
    __syncthreads();
    const float inv = 16256.f / __int_as_float(g_imax[1]);
#pragma unroll
    for (int k = 0; k < 4; ++k) {
        int tt = ty + 8 * k;
        int ah, al;
        quant15(tile[tx][tt], inv, ah, al);
        size_t o = ((size_t)z * T_LEN + t0 + tt) * CC + c0 + tx;
        g_x8h[o] = (int8_t)ah;
        g_x8l[o] = (int8_t)al;
    }
}

__global__ void __launch_bounds__(256) split_f32(
    const float* __restrict__ src, __nv_bfloat16* __restrict__ hi,
    __nv_bfloat16* __restrict__ lo, int n4)
{
    int i = blockIdx.x * blockDim.x + threadIdx.x;
    if (i >= n4) return;
    float4 v = ((const float4*)src)[i];
    uint32_t h0, l0, h1, l1;
    split2(v.x, v.y, h0, l0);
    split2(v.z, v.w, h1, l1);
    ((uint2*)hi)[i] = make_uint2(h0, h1);
    ((uint2*)lo)[i] = make_uint2(l0, l1);
}

// ===================== int8 two-limb QKV GEMM =====================
// C[z][M,N] = W[M,K] * x8T[z][N,K]^T ; CTA 128m x 64n, warp 32x32, k-slab 64
#define I8_ASTR 80
#define I8_A_HI 0
#define I8_A_LO 10240
#define I8_B_HI 20480
#define I8_B_LO 25600
#define I8_STAGE 30720
#define I8_SMEM (2 * I8_STAGE)

__global__ void __launch_bounds__(256, 2) gemm_i8qkv(const float* __restrict__ bias)
{
    extern __shared__ char sm[];
    const int M = 3 * CC, N = T_LEN, K = CC;
    const int z  = blockIdx.z;
    const int n0 = blockIdx.x * 64;
    const int m0 = blockIdx.y * 128;
    const int tid  = threadIdx.x;
    const int wid  = tid >> 5;
    const int lane = tid & 31;
    const int wm = wid & 3, wn = wid >> 2;

    const int8_t* Bh = g_x8h + (size_t)z * N * K;
    const int8_t* Bl = g_x8l + (size_t)z * N * K;

    int hh[2][4][4], mm[2][4][4];
#pragma unroll
    for (int a = 0; a < 2; ++a)
#pragma unroll
        for (int b = 0; b < 4; ++b)
#pragma unroll
            for (int e = 0; e < 4; ++e) { hh[a][b][e] = 0; mm[a][b][e] = 0; }

    const uint32_t smb = smem_u32(sm);
    const uint32_t aRel = I8_A_HI + (uint32_t)(wm * 32 + (lane & 15)) * I8_ASTR
                        + ((lane >> 4) << 4);
    const uint32_t bRel = I8_B_HI
                        + (uint32_t)(wn * 32 + (lane & 7) + ((lane >> 4) << 3)) * I8_ASTR
                        + (((lane >> 3) & 1) << 4);

    const int ar0 = tid >> 2,         ac0 = (tid & 3) << 4;
    const int ar1 = (tid + 256) >> 2, ac1 = ((tid + 256) & 3) << 4;
    const int br  = tid >> 2,         bc  = (tid & 3) << 4;

    auto load_slab = [&](int k0, int st) {
        uint32_t base = smb + (uint32_t)st * I8_STAGE;
        size_t ga0 = (size_t)(m0 + ar0) * K + k0 + ac0;
        size_t ga1 = (size_t)(m0 + ar1) * K + k0 + ac1;
        size_t gb  = (size_t)(n0 + br) * K + k0 + bc;
        cp16(base + I8_A_HI + ar0 * I8_ASTR + ac0, g_w8h + ga0);
        cp16(base + I8_A_LO + ar0 * I8_ASTR + ac0, g_w8l + ga0);
        cp16(base + I8_A_HI + ar1 * I8_ASTR + ac1, g_w8h + ga1);
        cp16(base + I8_A_LO + ar1 * I8_ASTR + ac1, g_w8l + ga1);
        cp16(base + I8_B_HI + br * I8_ASTR + bc, Bh + gb);
        cp16(base + I8_B_LO + br * I8_ASTR + bc, Bl + gb);
    };

    load_slab(0, 0);
    CP_COMMIT();

    int stage = 0;
    const int NSLAB = K >> 6;
    for (int it = 0; it < NSLAB; ++it) {
        CP_WAIT0();
        __syncthreads();
        if (it + 1 < NSLAB) { load_slab((it + 1) << 6, stage ^ 1); CP_COMMIT(); }

        const uint32_t aAddr = smb + (uint32_t)stage * I8_STAGE + aRel;
        const uint32_t bAddr = smb + (uint32_t)stage * I8_STAGE + bRel;
#pragma unroll
        for (int ks = 0; ks < 2; ++ks) {
            uint32_t bfh[2][4], bfl[2][4];
#pragma unroll
            for (int pr = 0; pr < 2; ++pr) {
                uint32_t ba = bAddr + pr * (16 * I8_ASTR) + ks * 32;
                ldsm4(bfh[pr][0], bfh[pr][1], bfh[pr][2], bfh[pr][3], ba);
                ldsm4(bfl[pr][0], bfl[pr][1], bfl[pr][2], bfl[pr][3],
                      ba + (I8_B_LO - I8_B_HI));
            }
#pragma unroll
            for (int mt = 0; mt < 2; ++mt) {
                uint32_t aa = aAddr + mt * (16 * I8_ASTR) + ks * 32;
                uint32_t ah0, ah1, ah2, ah3, al0, al1, al2, al3;
                ldsm4(ah0, ah1, ah2, ah3, aa);
                ldsm4(al0, al1, al2, al3, aa + (I8_A_LO - I8_A_HI));
#pragma unroll
                for (int ng = 0; ng < 4; ++ng) {
                    int pr = ng >> 1, o = (ng & 1) << 1;
                    imma16832(hh[mt][ng], ah0, ah1, ah2, ah3, bfh[pr][o], bfh[pr][o + 1]);
                    imma16832(mm[mt][ng], ah0, ah1, ah2, ah3, bfl[pr][o], bfl[pr][o + 1]);
                    imma16832(mm[mt][ng], al0, al1, al2, al3, bfh[pr][o], bfh[pr][o + 1]);
                }
            }
        }
        stage ^= 1;
    }

    const float sab = (__int_as_float(g_imax[0]) * (1.f / 16256.f)) *
                      (__int_as_float(g_imax[1]) * (1.f / 16256.f));
    __nv_bfloat16* ChZ = g_qkvhi + (size_t)z * M * N;
    __nv_bfloat16* ClZ = g_qkvlo + (size_t)z * M * N;
#pragma unroll
    for (int mt = 0; mt < 2; ++mt) {
        int r1 = m0 + wm * 32 + mt * 16 + (lane >> 2);
        int r2 = r1 + 8;
        float b1 = bias[r1], b2 = bias[r2];
#pragma unroll
        for (int ng = 0; ng < 4; ++ng) {
            int col = n0 + wn * 32 + ng * 8 + ((lane & 3) << 1);
            float v0 = sab * (16384.f * (float)hh[mt][ng][0] + 128.f * (float)mm[mt][ng][0]) + b1;
            float v1 = sab * (16384.f * (float)hh[mt][ng][1] + 128.f * (float)mm[mt][ng][1]) + b1;
            float v2 = sab * (16384.f * (float)hh[mt][ng][2] + 128.f * (float)mm[mt][ng][2]) + b2;
            float v3 = sab * (16384.f * (float)hh[mt][ng][3] + 128.f * (float)mm[mt][ng][3]) + b2;
            uint32_t h, l;
            split2(v0, v1, h, l);
            *(uint32_t*)(ChZ + (size_t)r1 * N + col) = h;
            *(uint32_t*)(ClZ + (size_t)r1 * N + col) = l;
            split2(v2, v3, h, l);
            *(uint32_t*)(ChZ + (size_t)r2 * N + col) = h;
            *(uint32_t*)(ClZ + (size_t)r2 * N + col) = l;
        }
    }
}

// ===================== bf16 3-term proj GEMM (R6, verified) =====================
#define ASTR 80
#define BSTR 272
#define SA_HI 0
#define SA_LO 10240
#define SB_HI 20480
#define SB_LO 29184
#define GSTAGE 37888
#define GEMM_SMEM (2 * GSTAGE)

__global__ void __launch_bounds__(256, 2) gemm_proj(
    const float* __restrict__ bias, const float* __restrict__ res, float* __restrict__ C)
{
    extern __shared__ char sm[];
    const int M = CC, N = T_LEN, K = CC;
    const int z  = blockIdx.z;
    const int n0 = blockIdx.x * 128;
    const int m0 = blockIdx.y * 128;
    const int tid  = threadIdx.x;
    const int wid  = tid >> 5;
    const int lane = tid & 31;
    const int wm = wid & 3, wn = wid >> 2;

    const __nv_bfloat16* Bhz = g_xhi + (size_t)z * K * N;
    const __nv_bfloat16* Blz = g_xlo + (size_t)z * K * N;

    float acc[2][8][4];
#pragma unroll
    for (int i = 0; i < 2; i++)
#pragma unroll
        for (int j = 0; j < 8; j++)
#pragma unroll
            for (int e = 0; e < 4; e++) acc[i][j][e] = 0.f;

    const uint32_t smb = smem_u32(sm);
    const int lr = lane & 15, lc = lane >> 4;
    const uint32_t aRel = SA_HI + (uint32_t)(wm * 32 + lr) * ASTR + lc * 16;
    const uint32_t bRel = SB_HI + (uint32_t)lr * BSTR + wn * 128 + lc * 16;

    const int am = tid >> 2, ak = (tid & 3) << 3;
    const int bk = tid >> 4, bn = (tid & 15) << 3;
    const int am2 = (tid + 256) >> 2, ak2 = ((tid + 256) & 3) << 3;
    const int bk2 = (tid + 256) >> 4, bn2 = ((tid + 256) & 15) << 3;

    auto load_slab = [&](int k0, int st) {
        uint32_t base = smb + (uint32_t)st * GSTAGE;
        size_t ga  = (size_t)(m0 + am)  * K + k0 + ak;
        size_t ga2 = (size_t)(m0 + am2) * K + k0 + ak2;
        size_t gb  = (size_t)(k0 + bk)  * N + n0 + bn;
        size_t gb2 = (size_t)(k0 + bk2) * N + n0 + bn2;
        cp16(base + SA_HI + am * ASTR + ak * 2,  g_whi + ga);
        cp16(base + SA_LO + am * ASTR + ak * 2,  g_wlo + ga);
        cp16(base + SA_HI + am2 * ASTR + ak2 * 2, g_whi + ga2);
        cp16(base + SA_LO + am2 * ASTR + ak2 * 2, g_wlo + ga2);
        cp16(base + SB_HI + bk * BSTR + bn * 2,  Bhz + gb);
        cp16(base + SB_LO + bk * BSTR + bn * 2,  Blz + gb);
        cp16(base + SB_HI + bk2 * BSTR + bn2 * 2, Bhz + gb2);
        cp16(base + SB_LO + bk2 * BSTR + bn2 * 2, Blz + gb2);
    };

    load_slab(0, 0);
    CP_COMMIT();

    int stage = 0;
    const int KS = K >> 5;
    for (int it = 0; it < KS; ++it) {
        CP_WAIT0();
        __syncthreads();
        if (it + 1 < KS) { load_slab((it + 1) << 5, stage ^ 1); CP_COMMIT(); }

        const uint32_t aAddr = smb + (uint32_t)stage * GSTAGE + aRel;
        const uint32_t bAddr = smb + (uint32_t)stage * GSTAGE + bRel;
#pragma unroll
        for (int ks = 0; ks < 2; ++ks) {
            uint32_t bh[4][4], bl[4][4];
#pragma unroll
            for (int g = 0; g < 4; ++g) {
                uint32_t base = bAddr + ks * (16 * BSTR) + g * 32;
                ldsm4t(bh[g][0], bh[g][1], bh[g][2], bh[g][3], base);
                ldsm4t(bl[g][0], bl[g][1], bl[g][2], bl[g][3], base + (SB_LO - SB_HI));
            }
#pragma unroll
            for (int mt = 0; mt < 2; ++mt) {
                uint32_t abase = aAddr + mt * (16 * ASTR) + ks * 32;
                uint32_t ah0, ah1, ah2, ah3, al0, al1, al2, al3;
                ldsm4(ah0, ah1, ah2, ah3, abase);
                ldsm4(al0, al1, al2, al3, abase + (SA_LO - SA_HI));
#pragma unroll
                for (int g = 0; g < 4; ++g) {
                    float* c0 = acc[mt][2 * g];
                    float* c1 = acc[mt][2 * g + 1];
                    mma16816(c0, ah0, ah1, ah2, ah3, bh[g][0], bh[g][1]);
                    mma16816(c0, ah0, ah1, ah2, ah3, bl[g][0], bl[g][1]);
                    mma16816(c0, al0, al1, al2, al3, bh[g][0], bh[g][1]);
                    mma16816(c1, ah0, ah1, ah2, ah3, bh[g][2], bh[g][3]);
                    mma16816(c1, ah0, ah1, ah2, ah3, bl[g][2], bl[g][3]);
                    mma16816(c1, al0, al1, al2, al3, bh[g][2], bh[g][3]);
                }
            }
        }
        stage ^= 1;
    }

#pragma unroll
    for (int mt = 0; mt < 2; ++mt) {
        int r1 = m0 + wm * 32 + mt * 16 + (lane >> 2);
        int r2 = r1 + 8;
        float b1 = bias[r1], b2 = bias[r2];
#pragma unroll
        for (int g = 0; g < 8; ++g) {
            int col = n0 + wn * 64 + g * 8 + ((lane & 3) << 1);
            float2 q1 = *(const float2*)(res + (size_t)z * M * N + (size_t)r1 * N + col);
            float2 q2 = *(const float2*)(res + (size_t)z * M * N + (size_t)r2 * N + col);
            *(float2*)(C + (size_t)z * M * N + (size_t)r1 * N + col) =
                make_float2(acc[mt][g][0] + b1 + q1.x, acc[mt][g][1] + b1 + q1.y);
            *(float2*)(C + (size_t)z * M * N + (size_t)r2 * N + col) =
                make_float2(acc[mt][g][2] + b2 + q2.x, acc[mt][g][3] + b2 + q2.y);
        }
    }
}

// ===================== attention (R6, verified) =====================
#define BT2 128
#define BS2 64
#define NIT (T_LEN / BS2)
#define QSTR 272
#define KSTR 144
#define SM_QHI 0
#define SM_QLO 17408
#define SM_KV  34816
#define KVS_K_HI 0
#define KVS_K_LO 9216
#define KVS_V_HI 18432
#define KVS_V_LO 27648
#define KVSTAGE 36864
#define ATTN_SMEM (SM_KV + 2 * KVSTAGE)

__global__ void __launch_bounds__(256, 2) attn_mma()
{
    extern __shared__ char sm[];
    const int tid  = threadIdx.x;
    const int wid  = tid >> 5;
    const int lane = tid & 31;
    const int t0 = blockIdx.x * BT2;
    const int h  = blockIdx.y;
    const int b  = blockIdx.z;

    const size_t qoff = ((size_t)b * 3 * CC + h * HD) * T_LEN;
    const __nv_bfloat16* qhi = g_qkvhi + qoff;
    const __nv_bfloat16* qlo = g_qkvlo + qoff;
    const __nv_bfloat16* khi = qhi + (size_t)CC * T_LEN;
    const __nv_bfloat16* klo = qlo + (size_t)CC * T_LEN;
    const __nv_bfloat16* vhi = khi + (size_t)CC * T_LEN;
    const __nv_bfloat16* vlo = klo + (size_t)CC * T_LEN;

    const uint32_t smb = smem_u32(sm);
    const int kvd = tid >> 3, kvc = tid & 7;
    const int kvd2 = (tid + 256) >> 3, kvc2 = (tid + 256) & 7;
    auto kv_load = [&](int s0, int st) {
        uint32_t base = smb + SM_KV + (uint32_t)st * KVSTAGE;
        size_t g  = (size_t)kvd * T_LEN + s0 + kvc * 8;
        size_t g2 = (size_t)kvd2 * T_LEN + s0 + kvc2 * 8;
        uint32_t o  = base + kvd * KSTR + kvc * 16;
        uint32_t o2 = base + kvd2 * KSTR + kvc2 * 16;
        cp16(o + KVS_K_HI,  khi + g);
        cp16(o + KVS_K_LO,  klo + g);
        cp16(o + KVS_V_HI,  vhi + g);
        cp16(o + KVS_V_LO,  vlo + g);
        cp16(o2 + KVS_K_HI, khi + g2);
        cp16(o2 + KVS_K_LO, klo + g2);
        cp16(o2 + KVS_V_HI, vhi + g2);
        cp16(o2 + KVS_V_LO, vlo + g2);
    };

    kv_load(0, 0);
    CP_COMMIT();

#pragma unroll
    for (int l = 0; l < 4; ++l) {
        int f = tid + l * 256;
        int d = f >> 4;
        int c = f & 15;
        size_t g = (size_t)d * T_LEN + t0 + c * 8;
        *(uint4*)(sm + SM_QHI + d * QSTR + c * 16) = *(const uint4*)(qhi + g);
        *(uint4*)(sm + SM_QLO + d * QSTR + c * 16) = *(const uint4*)(qlo + g);
    }

    float oacc[32];
#pragma unroll
    for (int i = 0; i < 32; ++i) oacc[i] = 0.f;
    float m_r1 = -INFINITY, m_r2 = -INFINITY, l_r1 = 0.f, l_r2 = 0.f;

    const int q8 = lane & 7;
    const int qh2 = (lane >> 3) & 1;
    const int qd2 = lane >> 4;
    const uint32_t qa_hi = smb + SM_QHI + (uint32_t)(q8 + 8 * qd2) * QSTR + wid * 32 + qh2 * 16;
    const uint32_t qa_lo = qa_hi + (SM_QLO - SM_QHI);
    const int lr = lane & 15, lc = lane >> 4;
    const uint32_t kb_rel = (uint32_t)lr * KSTR + lc * 16;
    const int v8 = lane & 7;
    const int vh2 = (lane >> 3) & 1;
    const int vd2 = lane >> 4;
    const uint32_t vb_rel = KVS_V_HI + (uint32_t)(v8 + 8 * vd2) * KSTR + vh2 * 16;

    const float scale = 0.044194173824159216f;

    int stage = 0;
    for (int it = 0; it < NIT; ++it) {
        CP_WAIT0();
        __syncthreads();
        if (it + 1 < NIT) { kv_load((it + 1) * BS2, stage ^ 1); CP_COMMIT(); }

        const uint32_t kvb = smb + SM_KV + (uint32_t)stage * KVSTAGE;
        const uint32_t kb_hi = kvb + kb_rel;
        const uint32_t kb_lo = kb_hi + KVS_K_LO;
        const uint32_t vb_hi = kvb + vb_rel;

        float sacc[32];
#pragma unroll
        for (int i = 0; i < 32; ++i) sacc[i] = 0.f;
#pragma unroll
        for (int ks = 0; ks < 4; ++ks) {
            uint32_t qh0, qh1, qh2r, qh3, ql0, ql1, ql2, ql3;
            ldsm4t(qh0, qh1, qh2r, qh3, qa_hi + ks * (16 * QSTR));
            ldsm4t(ql0, ql1, ql2, ql3, qa_lo + ks * (16 * QSTR));
#pragma unroll
            for (int np = 0; np < 4; ++np) {
                uint32_t bh0, bh1, bh2, bh3, bl0, bl1, bl2, bl3;
                ldsm4t(bh0, bh1, bh2, bh3, kb_hi + ks * (16 * KSTR) + np * 32);
                ldsm4t(bl0, bl1, bl2, bl3, kb_lo + ks * (16 * KSTR) + np * 32);
                float* c0 = &sacc[np * 8];
                float* c1 = &sacc[np * 8 + 4];
                mma16816(c0, qh0, qh1, qh2r, qh3, bh0, bh1);
                mma16816(c0, qh0, qh1, qh2r, qh3, bl0, bl1);
                mma16816(c0, ql0, ql1, ql2, ql3, bh0, bh1);
                mma16816(c1, qh0, qh1, qh2r, qh3, bh2, bh3);
                mma16816(c1, qh0, qh1, qh2r, qh3, bl2, bl3);
                mma16816(c1, ql0, ql1, ql2, ql3, bh2, bh3);
            }
        }

#pragma unroll
        for (int i = 0; i < 32; ++i) sacc[i] *= scale;
        float nm1 = -INFINITY, nm2 = -INFINITY;
#pragma unroll
        for (int j = 0; j < 8; ++j) {
            nm1 = fmaxf(nm1, fmaxf(sacc[4 * j],     sacc[4 * j + 1]));
            nm2 = fmaxf(nm2, fmaxf(sacc[4 * j + 2], sacc[4 * j + 3]));
        }
        nm1 = fmaxf(nm1, __shfl_xor_sync(0xffffffffu, nm1, 1));
        nm1 = fmaxf(nm1, __shfl_xor_sync(0xffffffffu, nm1, 2));
        nm2 = fmaxf(nm2, __shfl_xor_sync(0xffffffffu, nm2, 1));
        nm2 = fmaxf(nm2, __shfl_xor_sync(0xffffffffu, nm2, 2));
        const float mn1 = fmaxf(m_r1, nm1);
        const float mn2 = fmaxf(m_r2, nm2);
        const float a1 = __expf(m_r1 - mn1);
        const float a2 = __expf(m_r2 - mn2);
        float s1 = 0.f, s2 = 0.f;
#pragma unroll
        for (int j = 0; j < 8; ++j) {
            float e0 = __expf(sacc[4 * j]     - mn1);
            float e1 = __expf(sacc[4 * j + 1] - mn1);
            float e2 = __expf(sacc[4 * j + 2] - mn2);
            float e3 = __expf(sacc[4 * j + 3] - mn2);
            sacc[4 * j] = e0; sacc[4 * j + 1] = e1; sacc[4 * j + 2] = e2; sacc[4 * j + 3] = e3;
            s1 += e0 + e1;
            s2 += e2 + e3;
        }
        s1 += __shfl_xor_sync(0xffffffffu, s1, 1);
        s1 += __shfl_xor_sync(0xffffffffu, s1, 2);
        s2 += __shfl_xor_sync(0xffffffffu, s2, 1);
        s2 += __shfl_xor_sync(0xffffffffu, s2, 2);
        l_r1 = l_r1 * a1 + s1;
        l_r2 = l_r2 * a2 + s2;
        m_r1 = mn1;
        m_r2 = mn2;
#pragma unroll
        for (int j = 0; j < 8; ++j) {
            oacc[4 * j]     *= a1;
            oacc[4 * j + 1] *= a1;
            oacc[4 * j + 2] *= a2;
            oacc[4 * j + 3] *= a2;
        }

#pragma unroll
        for (int ks = 0; ks < 4; ++ks) {
            const float* sA = &sacc[8 * ks];
            uint32_t ph0, ph1, ph2, ph3, pl0, pl1, pl2, pl3;
            split2(sA[0], sA[1], ph0, pl0);
            split2(sA[2], sA[3], ph1, pl1);
            split2(sA[4], sA[5], ph2, pl2);
            split2(sA[6], sA[7], ph3, pl3);
#pragma unroll
            for (int np = 0; np < 4; ++np) {
                uint32_t bh0, bh1, bh2, bh3, bl0, bl1, bl2, bl3;
                uint32_t base = vb_hi + np * (16 * KSTR) + ks * 32;
                ldsm4(bh0, bh1, bh2, bh3, base);
                ldsm4(bl0, bl1, bl2, bl3, base + (KVS_V_LO - KVS_V_HI));
                float* c0 = &oacc[np * 8];
                float* c1 = &oacc[np * 8 + 4];
                mma16816(c0, ph0, ph1, ph2, ph3, bh0, bh1);
                mma16816(c0, ph0, ph1, ph2, ph3, bl0, bl1);
                mma16816(c0, pl0, pl1, pl2, pl3, bh0, bh1);
                mma16816(c1, ph0, ph1, ph2, ph3, bh2, bh3);
                mma16816(c1, ph0, ph1, ph2, ph3, bl2, bl3);
                mma16816(c1, pl0, pl1, pl2, pl3, bh2, bh3);
            }
        }
        stage ^= 1;
    }

    __syncthreads();
    {
        float* so = (float*)(sm + SM_KV);
        const float i1 = 1.f / l_r1;
        const float i2 = 1.f / l_r2;
        const int r  = lane >> 2;
        const int tw = wid * 16;
#pragma unroll
        for (int j = 0; j < 8; ++j) {
            int d0 = 8 * j + ((lane & 3) << 1);
            so[(size_t)d0 * 128 + tw + r]           = oacc[4 * j]     * i1;
            so[(size_t)(d0 + 1) * 128 + tw + r]     = oacc[4 * j + 1] * i1;
            so[(size_t)d0 * 128 + tw + r + 8]       = oacc[4 * j + 2] * i2;
            so[(size_t)(d0 + 1) * 128 + tw + r + 8] = oacc[4 * j + 3] * i2;
        }
        __syncthreads();
        const size_t obase = ((size_t)b * CC + h * HD) * T_LEN;
#pragma unroll
        for (int l = 0; l < 8; ++l) {
            int f  = tid + l * 256;
            int c  = f >> 5;
            int t4 = (f & 31) << 2;
            float4 v = *(float4*)&so[(size_t)c * 128 + t4];
            uint32_t h0, l0, h1, l1;
            split2(v.x, v.y, h0, l0);
            split2(v.z, v.w, h1, l1);
            size_t g = obase + (size_t)c * T_LEN + t0 + t4;
            *(uint2*)(g_xhi + g) = make_uint2(h0, h1);
            *(uint2*)(g_xlo + g) = make_uint2(l0, l1);
        }
    }
}

// ===================== launch =====================
extern "C" void kernel_launch(void* const* d_in, const int* in_sizes, int n_in,
                              void* d_out, int out_size)
{
    const float* x      = (const float*)d_in[0];
    const float* qkv_w  = (const float*)d_in[1];
    const float* qkv_b  = (const float*)d_in[2];
    const float* proj_w = (const float*)d_in[3];
    const float* proj_b = (const float*)d_in[4];
    float* out = (float*)d_out;

    __nv_bfloat16 *whi, *wlo;
    cudaGetSymbolAddress((void**)&whi, g_whi);
    cudaGetSymbolAddress((void**)&wlo, g_wlo);

    cudaFuncSetAttribute((const void*)attn_mma,
                         cudaFuncAttributeMaxDynamicSharedMemorySize, ATTN_SMEM);
    cudaFuncSetAttribute((const void*)gemm_i8qkv,
                         cudaFuncAttributeMaxDynamicSharedMemorySize, I8_SMEM);
    cudaFuncSetAttribute((const void*)gemm_proj,
                         cudaFuncAttributeMaxDynamicSharedMemorySize, GEMM_SMEM);

    init_scales<<<1, 32>>>();
    maxabs_f32<<<128, 256>>>((const float4*)qkv_w, QW_ELEMS / 4, 0);
    maxabs_f32<<<256, 256>>>((const float4*)x, (int)(X_ELEMS / 4), 1);
    quant_w<<<(QW_ELEMS + 255) / 256, 256>>>(qkv_w, QW_ELEMS);
    quant_xT<<<dim3(T_LEN / 32, CC / 32, BATCH), dim3(32, 8)>>>(x);
    split_f32<<<(PW_ELEMS / 4 + 255) / 256, 256>>>(proj_w, whi, wlo, PW_ELEMS / 4);

    gemm_i8qkv<<<dim3(T_LEN / 64, (3 * CC) / 128, BATCH), 256, I8_SMEM>>>(qkv_b);
    attn_mma<<<dim3(T_LEN / BT2, NH, BATCH), 256, ATTN_SMEM>>>();
    gemm_proj<<<dim3(T_LEN / 128, CC / 128, BATCH), 256, GEMM_SMEM>>>(proj_b, x, out);
}

// round 9
// speedup vs baseline: 1.3629x; 1.3629x over previous
#include <cuda_runtime.h>
#include <cuda_bf16.h>
#include <math.h>
#include <stdint.h>

#define CC     512
#define T_LEN  2048
#define BATCH  4
#define NH     8
#define HD     64

#define W_ELEMS (3 * CC * CC + CC * CC)             // qkv_w then proj_w
#define X_ELEMS ((size_t)BATCH * CC * T_LEN)
#define QKV_ELEMS ((size_t)BATCH * 3 * CC * T_LEN)
__device__ __nv_bfloat16 g_whi[W_ELEMS];
__device__ __nv_bfloat16 g_wlo[W_ELEMS];
__device__ __nv_bfloat16 g_xhi[X_ELEMS];            // x split, later attn output split
__device__ __nv_bfloat16 g_xlo[X_ELEMS];
__device__ __nv_bfloat16 g_qkvhi[QKV_ELEMS];
__device__ __nv_bfloat16 g_qkvlo[QKV_ELEMS];

// ===================== helpers =====================
__device__ __forceinline__ uint32_t smem_u32(const void* p) {
    uint32_t a;
    asm("{ .reg .u64 t; cvta.to.shared.u64 t, %1; cvt.u32.u64 %0, t; }" : "=r"(a) : "l"(p));
    return a;
}
__device__ __forceinline__ uint32_t pk_bf2(__nv_bfloat16 a, __nv_bfloat16 b) {
    __nv_bfloat162 t(a, b);
    return *reinterpret_cast<uint32_t*>(&t);
}
__device__ __forceinline__ void split2(float x, float y, uint32_t& hi, uint32_t& lo) {
    __nv_bfloat16 xh = __float2bfloat16(x), yh = __float2bfloat16(y);
    __nv_bfloat16 xl = __float2bfloat16(x - __bfloat162float(xh));
    __nv_bfloat16 yl = __float2bfloat16(y - __bfloat162float(yh));
    hi = pk_bf2(xh, yh);
    lo = pk_bf2(xl, yl);
}
__device__ __forceinline__ void ldsm4(uint32_t& r0, uint32_t& r1, uint32_t& r2, uint32_t& r3,
                                      uint32_t addr) {
    asm volatile("ldmatrix.sync.aligned.m8n8.x4.shared.b16 {%0,%1,%2,%3}, [%4];"
                 : "=r"(r0), "=r"(r1), "=r"(r2), "=r"(r3) : "r"(addr));
}
__device__ __forceinline__ void ldsm4t(uint32_t& r0, uint32_t& r1, uint32_t& r2, uint32_t& r3,
                                       uint32_t addr) {
    asm volatile("ldmatrix.sync.aligned.m8n8.x4.trans.shared.b16 {%0,%1,%2,%3}, [%4];"
                 : "=r"(r0), "=r"(r1), "=r"(r2), "=r"(r3) : "r"(addr));
}
__device__ __forceinline__ void mma16816(float* c, uint32_t a0, uint32_t a1, uint32_t a2,
                                         uint32_t a3, uint32_t b0, uint32_t b1) {
    asm volatile(
        "mma.sync.aligned.m16n8k16.row.col.f32.bf16.bf16.f32 "
        "{%0,%1,%2,%3}, {%4,%5,%6,%7}, {%8,%9}, {%0,%1,%2,%3};"
        : "+f"(c[0]), "+f"(c[1]), "+f"(c[2]), "+f"(c[3])
        : "r"(a0), "r"(a1), "r"(a2), "r"(a3), "r"(b0), "r"(b1));
}
__device__ __forceinline__ void cp16(uint32_t dst, const void* src) {
    asm volatile("cp.async.cg.shared.global [%0], [%1], 16;" :: "r"(dst), "l"(src));
}
#define CP_COMMIT() asm volatile("cp.async.commit_group;" ::: "memory")
#define CP_WAIT0()  asm volatile("cp.async.wait_group 0;" ::: "memory")

// ===================== prep: fp32 -> bf16 hi/lo =====================
__global__ void __launch_bounds__(256) split_f32(
    const float* __restrict__ src, __nv_bfloat16* __restrict__ hi,
    __nv_bfloat16* __restrict__ lo, int n4)
{
    int i = blockIdx.x * blockDim.x + threadIdx.x;
    if (i >= n4) return;
    float4 v = ((const float4*)src)[i];
    uint32_t h0, l0, h1, l1;
    split2(v.x, v.y, h0, l0);
    split2(v.z, v.w, h1, l1);
    ((uint2*)hi)[i] = make_uint2(h0, h1);
    ((uint2*)lo)[i] = make_uint2(l0, l1);
}

// ===================== bf16 3-term GEMM =====================
// CTA tile 64m x 128n x 32k, 8 warps (4m x 2n), warp tile 16x64, 2-stage cp.async
#define ASTR 80          // 32 bf16 + pad
#define BSTR 272         // 128 bf16 + pad
#define SA_HI 0
#define SA_LO 5120
#define SB_HI 10240
#define SB_LO 18944
#define GSTAGE 27648
#define GEMM_SMEM (2 * GSTAGE)

template<bool RES, bool SPLITOUT>
__global__ void __launch_bounds__(256, 3) gemm_bf16(
    const __nv_bfloat16* __restrict__ Ahi, const __nv_bfloat16* __restrict__ Alo,
    const __nv_bfloat16* __restrict__ Bhi, const __nv_bfloat16* __restrict__ Blo,
    const float* __restrict__ bias, const float* __restrict__ res,
    float* __restrict__ C, __nv_bfloat16* __restrict__ Chi, __nv_bfloat16* __restrict__ Clo,
    int M, int N, int K)
{
    extern __shared__ char sm[];
    const int z  = blockIdx.z;
    const int n0 = blockIdx.x * 128;
    const int m0 = blockIdx.y * 64;
    const int tid  = threadIdx.x;
    const int wid  = tid >> 5;
    const int lane = tid & 31;
    const int wm = wid & 3;          // 4 m-warps x 16 rows
    const int wn = wid >> 2;         // 2 n-warps x 64 cols

    const __nv_bfloat16* Bhz = Bhi + (size_t)z * K * N;
    const __nv_bfloat16* Blz = Blo + (size_t)z * K * N;

    float acc[8][4];
#pragma unroll
    for (int j = 0; j < 8; j++)
#pragma unroll
        for (int e = 0; e < 4; e++) acc[j][e] = 0.f;

    const uint32_t smb = smem_u32(sm);
    const int lr = lane & 15;
    const int lc = lane >> 4;
    const uint32_t aRel = SA_HI + (uint32_t)(wm * 16 + lr) * ASTR + lc * 16;
    const uint32_t bRel = SB_HI + (uint32_t)lr * BSTR + wn * 128 + lc * 16;

    // cp.async coords: A 64 rows x 64B (hi,lo); B 32 rows x 256B (hi,lo)
    const int ar = tid >> 2,  ac = (tid & 3) << 4;
    const int bk = tid >> 4,  bn = (tid & 15) << 3;
    const int bk2 = (tid + 256) >> 4, bn2 = ((tid + 256) & 15) << 3;

    const int KS = K >> 5;

    auto load_slab = [&](int k0, int st) {
        uint32_t base = smb + (uint32_t)st * GSTAGE;
        size_t ga  = (size_t)(m0 + ar) * K + k0 + (ac >> 1);
        size_t gb  = (size_t)(k0 + bk)  * N + n0 + bn;
        size_t gb2 = (size_t)(k0 + bk2) * N + n0 + bn2;
        cp16(base + SA_HI + ar * ASTR + ac, Ahi + ga);
        cp16(base + SA_LO + ar * ASTR + ac, Alo + ga);
        cp16(base + SB_HI + bk * BSTR + bn * 2,  Bhz + gb);
        cp16(base + SB_LO + bk * BSTR + bn * 2,  Blz + gb);
        cp16(base + SB_HI + bk2 * BSTR + bn2 * 2, Bhz + gb2);
        cp16(base + SB_LO + bk2 * BSTR + bn2 * 2, Blz + gb2);
    };

    load_slab(0, 0);
    CP_COMMIT();

    int stage = 0;
    for (int it = 0; it < KS; ++it) {
        CP_WAIT0();
        __syncthreads();
        if (it + 1 < KS) { load_slab((it + 1) << 5, stage ^ 1); CP_COMMIT(); }

        const uint32_t aAddr = smb + (uint32_t)stage * GSTAGE + aRel;
        const uint32_t bAddr = smb + (uint32_t)stage * GSTAGE + bRel;
#pragma unroll
        for (int ks = 0; ks < 2; ++ks) {
            uint32_t ah0, ah1, ah2, ah3, al0, al1, al2, al3;
            ldsm4(ah0, ah1, ah2, ah3, aAddr + ks * 32);
            ldsm4(al0, al1, al2, al3, aAddr + ks * 32 + (SA_LO - SA_HI));
#pragma unroll
            for (int g = 0; g < 4; ++g) {
                uint32_t bh0, bh1, bh2, bh3, bl0, bl1, bl2, bl3;
                uint32_t base = bAddr + ks * (16 * BSTR) + g * 32;
                ldsm4t(bh0, bh1, bh2, bh3, base);
                ldsm4t(bl0, bl1, bl2, bl3, base + (SB_LO - SB_HI));
                float* c0 = acc[2 * g];
                float* c1 = acc[2 * g + 1];
                mma16816(c0, ah0, ah1, ah2, ah3, bh0, bh1);
                mma16816(c0, ah0, ah1, ah2, ah3, bl0, bl1);
                mma16816(c0, al0, al1, al2, al3, bh0, bh1);
                mma16816(c1, ah0, ah1, ah2, ah3, bh2, bh3);
                mma16816(c1, ah0, ah1, ah2, ah3, bl2, bl3);
                mma16816(c1, al0, al1, al2, al3, bh2, bh3);
            }
        }
        stage ^= 1;
    }

    // ---- epilogue ----
    int r1 = m0 + wm * 16 + (lane >> 2);
    int r2 = r1 + 8;
    float b1 = bias[r1], b2 = bias[r2];
#pragma unroll
    for (int g = 0; g < 8; ++g) {
        int col = n0 + wn * 64 + g * 8 + ((lane & 3) << 1);
        float2 w1 = make_float2(acc[g][0] + b1, acc[g][1] + b1);
        float2 w2 = make_float2(acc[g][2] + b2, acc[g][3] + b2);
        if (SPLITOUT) {
            __nv_bfloat16* ChZ = Chi + (size_t)z * M * N;
            __nv_bfloat16* ClZ = Clo + (size_t)z * M * N;
            uint32_t hh, ll;
            split2(w1.x, w1.y, hh, ll);
            *(uint32_t*)(ChZ + (size_t)r1 * N + col) = hh;
            *(uint32_t*)(ClZ + (size_t)r1 * N + col) = ll;
            split2(w2.x, w2.y, hh, ll);
            *(uint32_t*)(ChZ + (size_t)r2 * N + col) = hh;
            *(uint32_t*)(ClZ + (size_t)r2 * N + col) = ll;
        } else {
            float* Cz = C + (size_t)z * M * N;
            if (RES) {
                float2 q1 = *(const float2*)(res + (size_t)z * M * N + (size_t)r1 * N + col);
                float2 q2 = *(const float2*)(res + (size_t)z * M * N + (size_t)r2 * N + col);
                w1.x += q1.x; w1.y += q1.y;
                w2.x += q2.x; w2.y += q2.y;
            }
            *(float2*)(Cz + (size_t)r1 * N + col) = w1;
            *(float2*)(Cz + (size_t)r2 * N + col) = w2;
        }
    }
}

// ===================== attention (R6, verified; exp2 domain) =====================
#define BT2 128
#define BS2 64
#define NIT (T_LEN / BS2)
#define QSTR 272
#define KSTR 144
#define SM_QHI 0
#define SM_QLO 17408
#define SM_KV  34816
#define KVS_K_HI 0
#define KVS_K_LO 9216
#define KVS_V_HI 18432
#define KVS_V_LO 27648
#define KVSTAGE 36864
#define ATTN_SMEM (SM_KV + 2 * KVSTAGE)

__global__ void __launch_bounds__(256, 2) attn_mma()
{
    extern __shared__ char sm[];
    const int tid  = threadIdx.x;
    const int wid  = tid >> 5;
    const int lane = tid & 31;
    const int t0 = blockIdx.x * BT2;
    const int h  = blockIdx.y;
    const int b  = blockIdx.z;

    const size_t qoff = ((size_t)b * 3 * CC + h * HD) * T_LEN;
    const __nv_bfloat16* qhi = g_qkvhi + qoff;
    const __nv_bfloat16* qlo = g_qkvlo + qoff;
    const __nv_bfloat16* khi = qhi + (size_t)CC * T_LEN;
    const __nv_bfloat16* klo = qlo + (size_t)CC * T_LEN;
    const __nv_bfloat16* vhi = khi + (size_t)CC * T_LEN;
    const __nv_bfloat16* vlo = klo + (size_t)CC * T_LEN;

    const uint32_t smb = smem_u32(sm);
    const int kvd = tid >> 3, kvc = tid & 7;
    const int kvd2 = (tid + 256) >> 3, kvc2 = (tid + 256) & 7;
    auto kv_load = [&](int s0, int st) {
        uint32_t base = smb + SM_KV + (uint32_t)st * KVSTAGE;
        size_t g  = (size_t)kvd * T_LEN + s0 + kvc * 8;
        size_t g2 = (size_t)kvd2 * T_LEN + s0 + kvc2 * 8;
        uint32_t o  = base + kvd * KSTR + kvc * 16;
        uint32_t o2 = base + kvd2 * KSTR + kvc2 * 16;
        cp16(o + KVS_K_HI,  khi + g);
        cp16(o + KVS_K_LO,  klo + g);
        cp16(o + KVS_V_HI,  vhi + g);
        cp16(o + KVS_V_LO,  vlo + g);
        cp16(o2 + KVS_K_HI, khi + g2);
        cp16(o2 + KVS_K_LO, klo + g2);
        cp16(o2 + KVS_V_HI, vhi + g2);
        cp16(o2 + KVS_V_LO, vlo + g2);
    };

    kv_load(0, 0);
    CP_COMMIT();

#pragma unroll
    for (int l = 0; l < 4; ++l) {
        int f = tid + l * 256;
        int d = f >> 4;
        int c = f & 15;
        size_t g = (size_t)d * T_LEN + t0 + c * 8;
        *(uint4*)(sm + SM_QHI + d * QSTR + c * 16) = *(const uint4*)(qhi + g);
        *(uint4*)(sm + SM_QLO + d * QSTR + c * 16) = *(const uint4*)(qlo + g);
    }

    float oacc[32];
#pragma unroll
    for (int i = 0; i < 32; ++i) oacc[i] = 0.f;
    float m_r1 = -INFINITY, m_r2 = -INFINITY, l_r1 = 0.f, l_r2 = 0.f;

    const int q8 = lane & 7;
    const int qh2 = (lane >> 3) & 1;
    const int qd2 = lane >> 4;
    const uint32_t qa_hi = smb + SM_QHI + (uint32_t)(q8 + 8 * qd2) * QSTR + wid * 32 + qh2 * 16;
    const uint32_t qa_lo = qa_hi + (SM_QLO - SM_QHI);
    const int lr = lane & 15, lc = lane >> 4;
    const uint32_t kb_rel = (uint32_t)lr * KSTR + lc * 16;
    const int v8 = lane & 7;
    const int vh2 = (lane >> 3) & 1;
    const int vd2 = lane >> 4;
    const uint32_t vb_rel = KVS_V_HI + (uint32_t)(v8 + 8 * vd2) * KSTR + vh2 * 16;

    // scale * log2(e): softmax in exp2 domain
    const float scale2 = 0.044194173824159216f * 1.4426950408889634f;

    int stage = 0;
    for (int it = 0; it < NIT; ++it) {
        CP_WAIT0();
        __syncthreads();
        if (it + 1 < NIT) { kv_load((it + 1) * BS2, stage ^ 1); CP_COMMIT(); }

        const uint32_t kvb = smb + SM_KV + (uint32_t)stage * KVSTAGE;
        const uint32_t kb_hi = kvb + kb_rel;
        const uint32_t kb_lo = kb_hi + KVS_K_LO;
        const uint32_t vb_hi = kvb + vb_rel;

        float sacc[32];
#pragma unroll
        for (int i = 0; i < 32; ++i) sacc[i] = 0.f;
#pragma unroll
        for (int ks = 0; ks < 4; ++ks) {
            uint32_t qh0, qh1, qh2r, qh3, ql0, ql1, ql2, ql3;
            ldsm4t(qh0, qh1, qh2r, qh3, qa_hi + ks * (16 * QSTR));
            ldsm4t(ql0, ql1, ql2, ql3, qa_lo + ks * (16 * QSTR));
#pragma unroll
            for (int np = 0; np < 4; ++np) {
                uint32_t bh0, bh1, bh2, bh3, bl0, bl1, bl2, bl3;
                ldsm4t(bh0, bh1, bh2, bh3, kb_hi + ks * (16 * KSTR) + np * 32);
                ldsm4t(bl0, bl1, bl2, bl3, kb_lo + ks * (16 * KSTR) + np * 32);
                float* c0 = &sacc[np * 8];
                float* c1 = &sacc[np * 8 + 4];
                mma16816(c0, qh0, qh1, qh2r, qh3, bh0, bh1);
                mma16816(c0, qh0, qh1, qh2r, qh3, bl0, bl1);
                mma16816(c0, ql0, ql1, ql2, ql3, bh0, bh1);
                mma16816(c1, qh0, qh1, qh2r, qh3, bh2, bh3);
                mma16816(c1, qh0, qh1, qh2r, qh3, bl2, bl3);
                mma16816(c1, ql0, ql1, ql2, ql3, bh2, bh3);
            }
        }

#pragma unroll
        for (int i = 0; i < 32; ++i) sacc[i] *= scale2;
        float nm1 = -INFINITY, nm2 = -INFINITY;
#pragma unroll
        for (int j = 0; j < 8; ++j) {
            nm1 = fmaxf(nm1, fmaxf(sacc[4 * j],     sacc[4 * j + 1]));
            nm2 = fmaxf(nm2, fmaxf(sacc[4 * j + 2], sacc[4 * j + 3]));
        }
        nm1 = fmaxf(nm1, __shfl_xor_sync(0xffffffffu, nm1, 1));
        nm1 = fmaxf(nm1, __shfl_xor_sync(0xffffffffu, nm1, 2));
        nm2 = fmaxf(nm2, __shfl_xor_sync(0xffffffffu, nm2, 1));
        nm2 = fmaxf(nm2, __shfl_xor_sync(0xffffffffu, nm2, 2));
        const float mn1 = fmaxf(m_r1, nm1);
        const float mn2 = fmaxf(m_r2, nm2);
        const float a1 = exp2f(m_r1 - mn1);
        const float a2 = exp2f(m_r2 - mn2);
        float s1 = 0.f, s2 = 0.f;
#pragma unroll
        for (int j = 0; j < 8; ++j) {
            float e0 = exp2f(sacc[4 * j]     - mn1);
            float e1 = exp2f(sacc[4 * j + 1] - mn1);
            float e2 = exp2f(sacc[4 * j + 2] - mn2);
            float e3 = exp2f(sacc[4 * j + 3] - mn2);
            sacc[4 * j] = e0; sacc[4 * j + 1] = e1; sacc[4 * j + 2] = e2; sacc[4 * j + 3] = e3;
            s1 += e0 + e1;
            s2 += e2 + e3;
        }
        s1 += __shfl_xor_sync(0xffffffffu, s1, 1);
        s1 += __shfl_xor_sync(0xffffffffu, s1, 2);
        s2 += __shfl_xor_sync(0xffffffffu, s2, 1);
        s2 += __shfl_xor_sync(0xffffffffu, s2, 2);
        l_r1 = l_r1 * a1 + s1;
        l_r2 = l_r2 * a2 + s2;
        m_r1 = mn1;
        m_r2 = mn2;
#pragma unroll
        for (int j = 0; j < 8; ++j) {
            oacc[4 * j]     *= a1;
            oacc[4 * j + 1] *= a1;
            oacc[4 * j + 2] *= a2;
            oacc[4 * j + 3] *= a2;
        }

#pragma unroll
        for (int ks = 0; ks < 4; ++ks) {
            const float* sA = &sacc[8 * ks];
            uint32_t ph0, ph1, ph2, ph3, pl0, pl1, pl2, pl3;
            split2(sA[0], sA[1], ph0, pl0);
            split2(sA[2], sA[3], ph1, pl1);
            split2(sA[4], sA[5], ph2, pl2);
            split2(sA[6], sA[7], ph3, pl3);
#pragma unroll
            for (int np = 0; np < 4; ++np) {
                uint32_t bh0, bh1, bh2, bh3, bl0, bl1, bl2, bl3;
                uint32_t base = vb_hi + np * (16 * KSTR) + ks * 32;
                ldsm4(bh0, bh1, bh2, bh3, base);
                ldsm4(bl0, bl1, bl2, bl3, base + (KVS_V_LO - KVS_V_HI));
                float* c0 = &oacc[np * 8];
                float* c1 = &oacc[np * 8 + 4];
                mma16816(c0, ph0, ph1, ph2, ph3, bh0, bh1);
                mma16816(c0, ph0, ph1, ph2, ph3, bl0, bl1);
                mma16816(c0, pl0, pl1, pl2, pl3, bh0, bh1);
                mma16816(c1, ph0, ph1, ph2, ph3, bh2, bh3);
                mma16816(c1, ph0, ph1, ph2, ph3, bl2, bl3);
                mma16816(c1, pl0, pl1, pl2, pl3, bh2, bh3);
            }
        }
        stage ^= 1;
    }

    __syncthreads();
    {
        float* so = (float*)(sm + SM_KV);
        const float i1 = 1.f / l_r1;
        const float i2 = 1.f / l_r2;
        const int r  = lane >> 2;
        const int tw = wid * 16;
#pragma unroll
        for (int j = 0; j < 8; ++j) {
            int d0 = 8 * j + ((lane & 3) << 1);
            so[(size_t)d0 * 128 + tw + r]           = oacc[4 * j]     * i1;
            so[(size_t)(d0 + 1) * 128 + tw + r]     = oacc[4 * j + 1] * i1;
            so[(size_t)d0 * 128 + tw + r + 8]       = oacc[4 * j + 2] * i2;
            so[(size_t)(d0 + 1) * 128 + tw + r + 8] = oacc[4 * j + 3] * i2;
        }
        __syncthreads();
        const size_t obase = ((size_t)b * CC + h * HD) * T_LEN;
#pragma unroll
        for (int l = 0; l < 8; ++l) {
            int f  = tid + l * 256;
            int c  = f >> 5;
            int t4 = (f & 31) << 2;
            float4 v = *(float4*)&so[(size_t)c * 128 + t4];
            uint32_t h0, l0, h1, l1;
            split2(v.x, v.y, h0, l0);
            split2(v.z, v.w, h1, l1);
            size_t g = obase + (size_t)c * T_LEN + t0 + t4;
            *(uint2*)(g_xhi + g) = make_uint2(h0, h1);
            *(uint2*)(g_xlo + g) = make_uint2(l0, l1);
        }
    }
}

// ===================== launch =====================
extern "C" void kernel_launch(void* const* d_in, const int* in_sizes, int n_in,
                              void* d_out, int out_size)
{
    const float* x      = (const float*)d_in[0];
    const float* qkv_w  = (const float*)d_in[1];
    const float* qkv_b  = (const float*)d_in[2];
    const float* proj_w = (const float*)d_in[3];
    const float* proj_b = (const float*)d_in[4];
    float* out = (float*)d_out;

    __nv_bfloat16 *whi, *wlo, *xhi, *xlo, *qkvhi, *qkvlo;
    cudaGetSymbolAddress((void**)&whi, g_whi);
    cudaGetSymbolAddress((void**)&wlo, g_wlo);
    cudaGetSymbolAddress((void**)&xhi, g_xhi);
    cudaGetSymbolAddress((void**)&xlo, g_xlo);
    cudaGetSymbolAddress((void**)&qkvhi, g_qkvhi);
    cudaGetSymbolAddress((void**)&qkvlo, g_qkvlo);

    cudaFuncSetAttribute((const void*)attn_mma,
                         cudaFuncAttributeMaxDynamicSharedMemorySize, ATTN_SMEM);
    cudaFuncSetAttribute((const void*)gemm_bf16<false, true>,
                         cudaFuncAttributeMaxDynamicSharedMemorySize, GEMM_SMEM);
    cudaFuncSetAttribute((const void*)gemm_bf16<true, false>,
                         cudaFuncAttributeMaxDynamicSharedMemorySize, GEMM_SMEM);

    const int QW4 = (3 * CC * CC) / 4;
    const int PW4 = (CC * CC) / 4;
    const int X4  = (int)(X_ELEMS / 4);
    const int PW_OFF = 3 * CC * CC;

    split_f32<<<(QW4 + 255) / 256, 256>>>(qkv_w, whi, wlo, QW4);
    split_f32<<<(PW4 + 255) / 256, 256>>>(proj_w, whi + PW_OFF, wlo + PW_OFF, PW4);
    split_f32<<<(X4 + 255) / 256, 256>>>(x, xhi, xlo, X4);

    // 1) qkv = W_qkv @ x + b  -> bf16 hi/lo
    gemm_bf16<false, true><<<dim3(T_LEN / 128, (3 * CC) / 64, BATCH), 256, GEMM_SMEM>>>(
        whi, wlo, xhi, xlo, qkv_b, nullptr, nullptr, qkvhi, qkvlo, 3 * CC, T_LEN, CC);

    // 2) attention (writes bf16 hi/lo into xhi/xlo)
    attn_mma<<<dim3(T_LEN / BT2, NH, BATCH), 256, ATTN_SMEM>>>();

    // 3) out = x + W_proj @ att + b  (fp32 out)
    gemm_bf16<true, false><<<dim3(T_LEN / 128, CC / 64, BATCH), 256, GEMM_SMEM>>>(
        whi + PW_OFF, wlo + PW_OFF, xhi, xlo, proj_b, x, out, nullptr, nullptr, CC, T_LEN, CC);
}

// round 11
// speedup vs baseline: 1.9269x; 1.4139x over previous
#include <cuda_runtime.h>
#include <cuda_fp16.h>
#include <math.h>
#include <stdint.h>

#define CC     512
#define T_LEN  2048
#define BATCH  4
#define NH     8
#define HD     64

#define W_ELEMS (3 * CC * CC + CC * CC)             // qkv_w then proj_w
#define X_ELEMS ((size_t)BATCH * CC * T_LEN)
#define QKV_ELEMS ((size_t)BATCH * 3 * CC * T_LEN)
__device__ __half g_wh[W_ELEMS];                    // weight hi limbs
__device__ __half g_wl[W_ELEMS];                    // weight lo limbs
__device__ __half g_xh[X_ELEMS];                    // x fp16, later attn-out fp16
__device__ __half g_qh[QKV_ELEMS];                  // qkv hi
__device__ __half g_ql[QKV_ELEMS];                  // qkv lo (only Q rows used)

// ===================== helpers =====================
__device__ __forceinline__ uint32_t smem_u32(const void* p) {
    uint32_t a;
    asm("{ .reg .u64 t; cvta.to.shared.u64 t, %1; cvt.u32.u64 %0, t; }" : "=r"(a) : "l"(p));
    return a;
}
__device__ __forceinline__ uint32_t pk_h2(__half a, __half b) {
    __half2 t(a, b);
    return *reinterpret_cast<uint32_t*>(&t);
}
__device__ __forceinline__ void splith(float x, float y, uint32_t& hi, uint32_t& lo) {
    __half xh = __float2half_rn(x), yh = __float2half_rn(y);
    __half xl = __float2half_rn(x - __half2float(xh));
    __half yl = __float2half_rn(y - __half2float(yh));
    hi = pk_h2(xh, yh);
    lo = pk_h2(xl, yl);
}
__device__ __forceinline__ void ldsm4(uint32_t& r0, uint32_t& r1, uint32_t& r2, uint32_t& r3,
                                      uint32_t addr) {
    asm volatile("ldmatrix.sync.aligned.m8n8.x4.shared.b16 {%0,%1,%2,%3}, [%4];"
                 : "=r"(r0), "=r"(r1), "=r"(r2), "=r"(r3) : "r"(addr));
}
__device__ __forceinline__ void ldsm4t(uint32_t& r0, uint32_t& r1, uint32_t& r2, uint32_t& r3,
                                       uint32_t addr) {
    asm volatile("ldmatrix.sync.aligned.m8n8.x4.trans.shared.b16 {%0,%1,%2,%3}, [%4];"
                 : "=r"(r0), "=r"(r1), "=r"(r2), "=r"(r3) : "r"(addr));
}
__device__ __forceinline__ void mma_h(float* c, uint32_t a0, uint32_t a1, uint32_t a2,
                                      uint32_t a3, uint32_t b0, uint32_t b1) {
    asm volatile(
        "mma.sync.aligned.m16n8k16.row.col.f32.f16.f16.f32 "
        "{%0,%1,%2,%3}, {%4,%5,%6,%7}, {%8,%9}, {%0,%1,%2,%3};"
        : "+f"(c[0]), "+f"(c[1]), "+f"(c[2]), "+f"(c[3])
        : "r"(a0), "r"(a1), "r"(a2), "r"(a3), "r"(b0), "r"(b1));
}
__device__ __forceinline__ void cp16(uint32_t dst, const void* src) {
    asm volatile("cp.async.cg.shared.global [%0], [%1], 16;" :: "r"(dst), "l"(src));
}
#define CP_COMMIT() asm volatile("cp.async.commit_group;" ::: "memory")
#define CP_WAIT0()  asm volatile("cp.async.wait_group 0;" ::: "memory")

// ===================== prep =====================
__global__ void __launch_bounds__(256) split_h(
    const float* __restrict__ src, __half* __restrict__ hi, __half* __restrict__ lo, int n4)
{
    int i = blockIdx.x * blockDim.x + threadIdx.x;
    if (i >= n4) return;
    float4 v = ((const float4*)src)[i];
    uint32_t h0, l0, h1, l1;
    splith(v.x, v.y, h0, l0);
    splith(v.z, v.w, h1, l1);
    ((uint2*)hi)[i] = make_uint2(h0, h1);
    ((uint2*)lo)[i] = make_uint2(l0, l1);
}
__global__ void __launch_bounds__(256) conv_h(
    const float* __restrict__ src, __half* __restrict__ dst, int n4)
{
    int i = blockIdx.x * blockDim.x + threadIdx.x;
    if (i >= n4) return;
    float4 v = ((const float4*)src)[i];
    uint32_t a = pk_h2(__float2half_rn(v.x), __float2half_rn(v.y));
    uint32_t b = pk_h2(__float2half_rn(v.z), __float2half_rn(v.w));
    ((uint2*)dst)[i] = make_uint2(a, b);
}

// ===================== fp16 2-term GEMM =====================
// C[z][M,N] = (Ah+Al)[M,K] * B[z][K,N], CTA 64m x 128n x 32k, 8 warps (4m x 2n)
#define ASTR 80          // 32 fp16 + pad
#define BSTR 272         // 128 fp16 + pad
#define SA_HI 0
#define SA_LO 5120
#define SB    10240
#define GSTAGE 18944
#define GEMM_SMEM (2 * GSTAGE)

template<bool RES, bool SPLITOUT>
__global__ void __launch_bounds__(256, 3) gemm_h(
    const __half* __restrict__ Ah, const __half* __restrict__ Al,
    const __half* __restrict__ B,
    const float* __restrict__ bias, const float* __restrict__ res,
    float* __restrict__ C, __half* __restrict__ Chi, __half* __restrict__ Clo,
    int M, int N, int K)
{
    extern __shared__ char sm[];
    const int z  = blockIdx.z;
    const int n0 = blockIdx.x * 128;
    const int m0 = blockIdx.y * 64;
    const int tid  = threadIdx.x;
    const int wid  = tid >> 5;
    const int lane = tid & 31;
    const int wm = wid & 3;
    const int wn = wid >> 2;

    const __half* Bz = B + (size_t)z * K * N;

    float acc[8][4];
#pragma unroll
    for (int j = 0; j < 8; j++)
#pragma unroll
        for (int e = 0; e < 4; e++) acc[j][e] = 0.f;

    const uint32_t smb = smem_u32(sm);
    const int lr = lane & 15;
    const int lc = lane >> 4;
    const uint32_t aRel = SA_HI + (uint32_t)(wm * 16 + lr) * ASTR + lc * 16;
    const uint32_t bRel = SB + (uint32_t)lr * BSTR + wn * 128 + lc * 16;  // 64 fp16 cols = 128 B

    // cp.async coords
    const int ar = tid >> 2,  ac = (tid & 3) << 3;        // A: 64 rows x 4 chunks(8 elems)
    const int bk = tid >> 4,  bn = (tid & 15) << 3;       // B: 16 rows x 16 chunks / round
    const int bk2 = bk + 16;

    const int KS = K >> 5;

    auto load_slab = [&](int k0, int st) {
        uint32_t base = smb + (uint32_t)st * GSTAGE;
        size_t ga  = (size_t)(m0 + ar) * K + k0 + ac;
        size_t gb  = (size_t)(k0 + bk)  * N + n0 + bn;
        size_t gb2 = (size_t)(k0 + bk2) * N + n0 + bn;
        cp16(base + SA_HI + ar * ASTR + ac * 2, Ah + ga);
        cp16(base + SA_LO + ar * ASTR + ac * 2, Al + ga);
        cp16(base + SB + bk * BSTR + bn * 2,  Bz + gb);
        cp16(base + SB + bk2 * BSTR + bn * 2, Bz + gb2);
    };

    load_slab(0, 0);
    CP_COMMIT();

    int stage = 0;
    for (int it = 0; it < KS; ++it) {
        CP_WAIT0();
        __syncthreads();
        if (it + 1 < KS) { load_slab((it + 1) << 5, stage ^ 1); CP_COMMIT(); }

        const uint32_t aAddr = smb + (uint32_t)stage * GSTAGE + aRel;
        const uint32_t bAddr = smb + (uint32_t)stage * GSTAGE + bRel;
#pragma unroll
        for (int ks = 0; ks < 2; ++ks) {
            uint32_t ah0, ah1, ah2, ah3, al0, al1, al2, al3;
            ldsm4(ah0, ah1, ah2, ah3, aAddr + ks * 32);
            ldsm4(al0, al1, al2, al3, aAddr + ks * 32 + (SA_LO - SA_HI));
#pragma unroll
            for (int g = 0; g < 4; ++g) {
                uint32_t b0, b1, b2, b3;
                ldsm4t(b0, b1, b2, b3, bAddr + ks * (16 * BSTR) + g * 32);
                float* c0 = acc[2 * g];
                float* c1 = acc[2 * g + 1];
                mma_h(c0, ah0, ah1, ah2, ah3, b0, b1);
                mma_h(c0, al0, al1, al2, al3, b0, b1);
                mma_h(c1, ah0, ah1, ah2, ah3, b2, b3);
                mma_h(c1, al0, al1, al2, al3, b2, b3);
            }
        }
        stage ^= 1;
    }

    // ---- epilogue ----
    int r1 = m0 + wm * 16 + (lane >> 2);
    int r2 = r1 + 8;
    float b1 = bias[r1], b2 = bias[r2];
#pragma unroll
    for (int g = 0; g < 8; ++g) {
        int col = n0 + wn * 64 + g * 8 + ((lane & 3) << 1);
        float2 w1 = make_float2(acc[g][0] + b1, acc[g][1] + b1);
        float2 w2 = make_float2(acc[g][2] + b2, acc[g][3] + b2);
        if (SPLITOUT) {
            __half* ChZ = Chi + (size_t)z * M * N;
            __half* ClZ = Clo + (size_t)z * M * N;
            uint32_t hh, ll;
            splith(w1.x, w1.y, hh, ll);
            *(uint32_t*)(ChZ + (size_t)r1 * N + col) = hh;
            *(uint32_t*)(ClZ + (size_t)r1 * N + col) = ll;
            splith(w2.x, w2.y, hh, ll);
            *(uint32_t*)(ChZ + (size_t)r2 * N + col) = hh;
            *(uint32_t*)(ClZ + (size_t)r2 * N + col) = ll;
        } else {
            float* Cz = C + (size_t)z * M * N;
            if (RES) {
                float2 q1 = *(const float2*)(res + (size_t)z * M * N + (size_t)r1 * N + col);
                float2 q2 = *(const float2*)(res + (size_t)z * M * N + (size_t)r2 * N + col);
                w1.x += q1.x; w1.y += q1.y;
                w2.x += q2.x; w2.y += q2.y;
            }
            *(float2*)(Cz + (size_t)r1 * N + col) = w1;
            *(float2*)(Cz + (size_t)r2 * N + col) = w2;
        }
    }
}

// ===================== attention: fp16 2-term =====================
// Q = Qh+Ql (split), K,V single fp16.
#define BT2 128
#define BS2 64
#define NIT (T_LEN / BS2)
#define QSTR 272
#define KSTR 144
#define SM_QHI 0
#define SM_QLO 17408
#define SM_KV  34816
#define KVS_K  0
#define KVS_V  9216
#define KVSTAGE 18432
#define ATTN_SMEM (SM_KV + 2 * KVSTAGE)   // 71680

__global__ void __launch_bounds__(256, 2) attn_mma()
{
    extern __shared__ char sm[];
    const int tid  = threadIdx.x;
    const int wid  = tid >> 5;
    const int lane = tid & 31;
    const int t0 = blockIdx.x * BT2;
    const int h  = blockIdx.y;
    const int b  = blockIdx.z;

    const size_t qoff = ((size_t)b * 3 * CC + h * HD) * T_LEN;
    const __half* qhi = g_qh + qoff;
    const __half* qlo = g_ql + qoff;
    const __half* kh  = qhi + (size_t)CC * T_LEN;
    const __half* vh  = kh + (size_t)CC * T_LEN;

    const uint32_t smb = smem_u32(sm);
    // K/V loader: [d=64][s=64] fp16, 8 chunks/row
    const int kvd = tid >> 3, kvc = tid & 7;
    const int kvd2 = kvd + 32;
    auto kv_load = [&](int s0, int st) {
        uint32_t base = smb + SM_KV + (uint32_t)st * KVSTAGE;
        size_t g  = (size_t)kvd * T_LEN + s0 + kvc * 8;
        size_t g2 = (size_t)kvd2 * T_LEN + s0 + kvc * 8;
        uint32_t o  = base + kvd * KSTR + kvc * 16;
        uint32_t o2 = base + kvd2 * KSTR + kvc * 16;
        cp16(o + KVS_K,  kh + g);
        cp16(o + KVS_V,  vh + g);
        cp16(o2 + KVS_K, kh + g2);
        cp16(o2 + KVS_V, vh + g2);
    };

    kv_load(0, 0);
    CP_COMMIT();

    // Q tile [d=64][t=128] hi/lo, 16 chunks/row
#pragma unroll
    for (int l = 0; l < 4; ++l) {
        int f = tid + l * 256;
        int d = f >> 4;
        int c = f & 15;
        size_t g = (size_t)d * T_LEN + t0 + c * 8;
        *(uint4*)(sm + SM_QHI + d * QSTR + c * 16) = *(const uint4*)(qhi + g);
        *(uint4*)(sm + SM_QLO + d * QSTR + c * 16) = *(const uint4*)(qlo + g);
    }

    float oacc[32];
#pragma unroll
    for (int i = 0; i < 32; ++i) oacc[i] = 0.f;
    float m_r1 = -INFINITY, m_r2 = -INFINITY, l_r1 = 0.f, l_r2 = 0.f;

    const int q8 = lane & 7;
    const int qh2 = (lane >> 3) & 1;
    const int qd2 = lane >> 4;
    const uint32_t qa_hi = smb + SM_QHI + (uint32_t)(q8 + 8 * qd2) * QSTR + wid * 32 + qh2 * 16;
    const uint32_t qa_lo = qa_hi + (SM_QLO - SM_QHI);
    const int lr = lane & 15, lc = lane >> 4;
    const uint32_t kb_rel = KVS_K + (uint32_t)lr * KSTR + lc * 16;
    const int v8 = lane & 7;
    const int vh2b = (lane >> 3) & 1;
    const int vd2 = lane >> 4;
    const uint32_t vb_rel = KVS_V + (uint32_t)(v8 + 8 * vd2) * KSTR + vh2b * 16;

    const float scale2 = 0.044194173824159216f * 1.4426950408889634f;  // 512^-.5 * log2e

    int stage = 0;
    for (int it = 0; it < NIT; ++it) {
        CP_WAIT0();
        __syncthreads();
        if (it + 1 < NIT) { kv_load((it + 1) * BS2, stage ^ 1); CP_COMMIT(); }

        const uint32_t kvb = smb + SM_KV + (uint32_t)stage * KVSTAGE;
        const uint32_t kb = kvb + kb_rel;
        const uint32_t vb = kvb + vb_rel;

        // ---- S = Q K^T (2-term) ----
        float sacc[32];
#pragma unroll
        for (int i = 0; i < 32; ++i) sacc[i] = 0.f;
#pragma unroll
        for (int ks = 0; ks < 4; ++ks) {
            uint32_t qh0, qh1, qh2r, qh3, ql0, ql1, ql2, ql3;
            ldsm4t(qh0, qh1, qh2r, qh3, qa_hi + ks * (16 * QSTR));
            ldsm4t(ql0, ql1, ql2, ql3, qa_lo + ks * (16 * QSTR));
#pragma unroll
            for (int np = 0; np < 4; ++np) {
                uint32_t b0, b1, b2, b3;
                ldsm4t(b0, b1, b2, b3, kb + ks * (16 * KSTR) + np * 32);
                float* c0 = &sacc[np * 8];
                float* c1 = &sacc[np * 8 + 4];
                mma_h(c0, qh0, qh1, qh2r, qh3, b0, b1);
                mma_h(c0, ql0, ql1, ql2, ql3, b0, b1);
                mma_h(c1, qh0, qh1, qh2r, qh3, b2, b3);
                mma_h(c1, ql0, ql1, ql2, ql3, b2, b3);
            }
        }

        // ---- softmax (exp2 domain) ----
#pragma unroll
        for (int i = 0; i < 32; ++i) sacc[i] *= scale2;
        float nm1 = -INFINITY, nm2 = -INFINITY;
#pragma unroll
        for (int j = 0; j < 8; ++j) {
            nm1 = fmaxf(nm1, fmaxf(sacc[4 * j],     sacc[4 * j + 1]));
            nm2 = fmaxf(nm2, fmaxf(sacc[4 * j + 2], sacc[4 * j + 3]));
        }
        nm1 = fmaxf(nm1, __shfl_xor_sync(0xffffffffu, nm1, 1));
        nm1 = fmaxf(nm1, __shfl_xor_sync(0xffffffffu, nm1, 2));
        nm2 = fmaxf(nm2, __shfl_xor_sync(0xffffffffu, nm2, 1));
        nm2 = fmaxf(nm2, __shfl_xor_sync(0xffffffffu, nm2, 2));
        const float mn1 = fmaxf(m_r1, nm1);
        const float mn2 = fmaxf(m_r2, nm2);
        const float a1 = exp2f(m_r1 - mn1);
        const float a2 = exp2f(m_r2 - mn2);
        float s1 = 0.f, s2 = 0.f;
#pragma unroll
        for (int j = 0; j < 8; ++j) {
            float e0 = exp2f(sacc[4 * j]     - mn1);
            float e1 = exp2f(sacc[4 * j + 1] - mn1);
            float e2 = exp2f(sacc[4 * j + 2] - mn2);
            float e3 = exp2f(sacc[4 * j + 3] - mn2);
            sacc[4 * j] = e0; sacc[4 * j + 1] = e1; sacc[4 * j + 2] = e2; sacc[4 * j + 3] = e3;
            s1 += e0 + e1;
            s2 += e2 + e3;
        }
        s1 += __shfl_xor_sync(0xffffffffu, s1, 1);
        s1 += __shfl_xor_sync(0xffffffffu, s1, 2);
        s2 += __shfl_xor_sync(0xffffffffu, s2, 1);
        s2 += __shfl_xor_sync(0xffffffffu, s2, 2);
        l_r1 = l_r1 * a1 + s1;
        l_r2 = l_r2 * a2 + s2;
        m_r1 = mn1;
        m_r2 = mn2;
#pragma unroll
        for (int j = 0; j < 8; ++j) {
            oacc[4 * j]     *= a1;
            oacc[4 * j + 1] *= a1;
            oacc[4 * j + 2] *= a2;
            oacc[4 * j + 3] *= a2;
        }

        // ---- O += P V^T (2-term) ----
#pragma unroll
        for (int ks = 0; ks < 4; ++ks) {
            const float* sA = &sacc[8 * ks];
            uint32_t ph0, ph1, ph2, ph3, pl0, pl1, pl2, pl3;
            splith(sA[0], sA[1], ph0, pl0);
            splith(sA[2], sA[3], ph1, pl1);
            splith(sA[4], sA[5], ph2, pl2);
            splith(sA[6], sA[7], ph3, pl3);
#pragma unroll
            for (int np = 0; np < 4; ++np) {
                uint32_t b0, b1, b2, b3;
                ldsm4(b0, b1, b2, b3, vb + np * (16 * KSTR) + ks * 32);
                float* c0 = &oacc[np * 8];
                float* c1 = &oacc[np * 8 + 4];
                mma_h(c0, ph0, ph1, ph2, ph3, b0, b1);
                mma_h(c0, pl0, pl1, pl2, pl3, b0, b1);
                mma_h(c1, ph0, ph1, ph2, ph3, b2, b3);
                mma_h(c1, pl0, pl1, pl2, pl3, b2, b3);
            }
        }
        stage ^= 1;
    }

    __syncthreads();
    // ---- epilogue: normalize, stage [d][t] fp32, write fp16 single ----
    {
        float* so = (float*)(sm + SM_KV);
        const float i1 = 1.f / l_r1;
        const float i2 = 1.f / l_r2;
        const int r  = lane >> 2;
        const int tw = wid * 16;
#pragma unroll
        for (int j = 0; j < 8; ++j) {
            int d0 = 8 * j + ((lane & 3) << 1);
            so[(size_t)d0 * 128 + tw + r]           = oacc[4 * j]     * i1;
            so[(size_t)(d0 + 1) * 128 + tw + r]     = oacc[4 * j + 1] * i1;
            so[(size_t)d0 * 128 + tw + r + 8]       = oacc[4 * j + 2] * i2;
            so[(size_t)(d0 + 1) * 128 + tw + r + 8] = oacc[4 * j + 3] * i2;
        }
        __syncthreads();
        const size_t obase = ((size_t)b * CC + h * HD) * T_LEN;
#pragma unroll
        for (int l = 0; l < 8; ++l) {
            int f  = tid + l * 256;
            int c  = f >> 5;
            int t4 = (f & 31) << 2;
            float4 v = *(float4*)&so[(size_t)c * 128 + t4];
            uint32_t a = pk_h2(__float2half_rn(v.x), __float2half_rn(v.y));
            uint32_t d = pk_h2(__float2half_rn(v.z), __float2half_rn(v.w));
            *(uint2*)(g_xh + obase + (size_t)c * T_LEN + t0 + t4) = make_uint2(a, d);
        }
    }
}

// ===================== launch =====================
extern "C" void kernel_launch(void* const* d_in, const int* in_sizes, int n_in,
                              void* d_out, int out_size)
{
    const float* x      = (const float*)d_in[0];
    const float* qkv_w  = (const float*)d_in[1];
    const float* qkv_b  = (const float*)d_in[2];
    const float* proj_w = (const float*)d_in[3];
    const float* proj_b = (const float*)d_in[4];
    float* out = (float*)d_out;

    __half *wh, *wl, *xh, *qh, *ql;
    cudaGetSymbolAddress((void**)&wh, g_wh);
    cudaGetSymbolAddress((void**)&wl, g_wl);
    cudaGetSymbolAddress((void**)&xh, g_xh);
    cudaGetSymbolAddress((void**)&qh, g_qh);
    cudaGetSymbolAddress((void**)&ql, g_ql);

    cudaFuncSetAttribute((const void*)attn_mma,
                         cudaFuncAttributeMaxDynamicSharedMemorySize, ATTN_SMEM);
    cudaFuncSetAttribute((const void*)gemm_h<false, true>,
                         cudaFuncAttributeMaxDynamicSharedMemorySize, GEMM_SMEM);
    cudaFuncSetAttribute((const void*)gemm_h<true, false>,
                         cudaFuncAttributeMaxDynamicSharedMemorySize, GEMM_SMEM);

    const int QW4 = (3 * CC * CC) / 4;
    const int PW4 = (CC * CC) / 4;
    const int X4  = (int)(X_ELEMS / 4);
    const int PW_OFF = 3 * CC * CC;

    split_h<<<(QW4 + 255) / 256, 256>>>(qkv_w, wh, wl, QW4);
    split_h<<<(PW4 + 255) / 256, 256>>>(proj_w, wh + PW_OFF, wl + PW_OFF, PW4);
    conv_h<<<(X4 + 255) / 256, 256>>>(x, xh, X4);

    // 1) qkv = W_qkv @ x + b  -> fp16 hi/lo
    gemm_h<false, true><<<dim3(T_LEN / 128, (3 * CC) / 64, BATCH), 256, GEMM_SMEM>>>(
        wh, wl, xh, qkv_b, nullptr, nullptr, qh, ql, 3 * CC, T_LEN, CC);

    // 2) attention (writes fp16 into xh)
    attn_mma<<<dim3(T_LEN / BT2, NH, BATCH), 256, ATTN_SMEM>>>();

    // 3) out = x + W_proj @ att + b
    gemm_h<true, false><<<dim3(T_LEN / 128, CC / 64, BATCH), 256, GEMM_SMEM>>>(
        wh + PW_OFF, wl + PW_OFF, xh, proj_b, x, out, nullptr, nullptr, CC, T_LEN, CC);
}

// round 12
// speedup vs baseline: 2.9125x; 1.5115x over previous
#include <cuda_runtime.h>
#include <cuda_fp16.h>
#include <math.h>
#include <stdint.h>

#define CC     512
#define T_LEN  2048
#define BATCH  4
#define NH     8
#define HD     64

#define W_ELEMS (3 * CC * CC + CC * CC)             // qkv_w then proj_w
#define X_ELEMS ((size_t)BATCH * CC * T_LEN)
#define QKV_ELEMS ((size_t)BATCH * 3 * CC * T_LEN)
__device__ __half g_wh[W_ELEMS];                    // weights fp16
__device__ __half g_xh[X_ELEMS];                    // x fp16, later attn-out fp16
__device__ __half g_qh[QKV_ELEMS];                  // qkv fp16

// ===================== helpers =====================
__device__ __forceinline__ uint32_t smem_u32(const void* p) {
    uint32_t a;
    asm("{ .reg .u64 t; cvta.to.shared.u64 t, %1; cvt.u32.u64 %0, t; }" : "=r"(a) : "l"(p));
    return a;
}
__device__ __forceinline__ uint32_t pk_h2(__half a, __half b) {
    __half2 t(a, b);
    return *reinterpret_cast<uint32_t*>(&t);
}
__device__ __forceinline__ void ldsm4(uint32_t& r0, uint32_t& r1, uint32_t& r2, uint32_t& r3,
                                      uint32_t addr) {
    asm volatile("ldmatrix.sync.aligned.m8n8.x4.shared.b16 {%0,%1,%2,%3}, [%4];"
                 : "=r"(r0), "=r"(r1), "=r"(r2), "=r"(r3) : "r"(addr));
}
__device__ __forceinline__ void ldsm4t(uint32_t& r0, uint32_t& r1, uint32_t& r2, uint32_t& r3,
                                       uint32_t addr) {
    asm volatile("ldmatrix.sync.aligned.m8n8.x4.trans.shared.b16 {%0,%1,%2,%3}, [%4];"
                 : "=r"(r0), "=r"(r1), "=r"(r2), "=r"(r3) : "r"(addr));
}
__device__ __forceinline__ void mma_h(float* c, uint32_t a0, uint32_t a1, uint32_t a2,
                                      uint32_t a3, uint32_t b0, uint32_t b1) {
    asm volatile(
        "mma.sync.aligned.m16n8k16.row.col.f32.f16.f16.f32 "
        "{%0,%1,%2,%3}, {%4,%5,%6,%7}, {%8,%9}, {%0,%1,%2,%3};"
        : "+f"(c[0]), "+f"(c[1]), "+f"(c[2]), "+f"(c[3])
        : "r"(a0), "r"(a1), "r"(a2), "r"(a3), "r"(b0), "r"(b1));
}
__device__ __forceinline__ void cp16(uint32_t dst, const void* src) {
    asm volatile("cp.async.cg.shared.global [%0], [%1], 16;" :: "r"(dst), "l"(src));
}
#define CP_COMMIT() asm volatile("cp.async.commit_group;" ::: "memory")
#define CP_WAIT0()  asm volatile("cp.async.wait_group 0;" ::: "memory")

// ===================== prep: fp32 -> fp16 =====================
__global__ void __launch_bounds__(256) conv_h(
    const float* __restrict__ src, __half* __restrict__ dst, int n4)
{
    int i = blockIdx.x * blockDim.x + threadIdx.x;
    if (i >= n4) return;
    float4 v = ((const float4*)src)[i];
    uint32_t a = pk_h2(__float2half_rn(v.x), __float2half_rn(v.y));
    uint32_t b = pk_h2(__float2half_rn(v.z), __float2half_rn(v.w));
    ((uint2*)dst)[i] = make_uint2(a, b);
}

// ===================== fp16 single GEMM =====================
// C[z][M,N] = A[M,K] * B[z][K,N], CTA 64m x 128n x 32k, 8 warps (4m x 2n)
#define ASTR 80          // 32 fp16 + pad
#define BSTR 272         // 128 fp16 + pad
#define SA    0
#define SB    5120
#define GSTAGE 13824
#define GEMM_SMEM (2 * GSTAGE)

template<bool RES, bool SPLITOUT>
__global__ void __launch_bounds__(256, 3) gemm_h(
    const __half* __restrict__ A, const __half* __restrict__ B,
    const float* __restrict__ bias, const float* __restrict__ res,
    float* __restrict__ C, __half* __restrict__ Ch,
    int M, int N, int K)
{
    extern __shared__ char sm[];
    const int z  = blockIdx.z;
    const int n0 = blockIdx.x * 128;
    const int m0 = blockIdx.y * 64;
    const int tid  = threadIdx.x;
    const int wid  = tid >> 5;
    const int lane = tid & 31;
    const int wm = wid & 3;
    const int wn = wid >> 2;

    const __half* Bz = B + (size_t)z * K * N;

    float acc[8][4];
#pragma unroll
    for (int j = 0; j < 8; j++)
#pragma unroll
        for (int e = 0; e < 4; e++) acc[j][e] = 0.f;

    const uint32_t smb = smem_u32(sm);
    const int lr = lane & 15;
    const int lc = lane >> 4;
    const uint32_t aRel = SA + (uint32_t)(wm * 16 + lr) * ASTR + lc * 16;
    const uint32_t bRel = SB + (uint32_t)lr * BSTR + wn * 128 + lc * 16;

    // cp.async coords
    const int ar = tid >> 2,  ac = (tid & 3) << 3;        // A: 64 rows x 4 chunks
    const int bk = tid >> 4,  bn = (tid & 15) << 3;       // B: 16 rows x 16 chunks / round
    const int bk2 = bk + 16;

    const int KS = K >> 5;

    auto load_slab = [&](int k0, int st) {
        uint32_t base = smb + (uint32_t)st * GSTAGE;
        size_t ga  = (size_t)(m0 + ar) * K + k0 + ac;
        size_t gb  = (size_t)(k0 + bk)  * N + n0 + bn;
        size_t gb2 = (size_t)(k0 + bk2) * N + n0 + bn;
        cp16(base + SA + ar * ASTR + ac * 2, A + ga);
        cp16(base + SB + bk * BSTR + bn * 2,  Bz + gb);
        cp16(base + SB + bk2 * BSTR + bn * 2, Bz + gb2);
    };

    load_slab(0, 0);
    CP_COMMIT();

    int stage = 0;
    for (int it = 0; it < KS; ++it) {
        CP_WAIT0();
        __syncthreads();
        if (it + 1 < KS) { load_slab((it + 1) << 5, stage ^ 1); CP_COMMIT(); }

        const uint32_t aAddr = smb + (uint32_t)stage * GSTAGE + aRel;
        const uint32_t bAddr = smb + (uint32_t)stage * GSTAGE + bRel;
#pragma unroll
        for (int ks = 0; ks < 2; ++ks) {
            uint32_t a0, a1, a2, a3;
            ldsm4(a0, a1, a2, a3, aAddr + ks * 32);
#pragma unroll
            for (int g = 0; g < 4; ++g) {
                uint32_t b0, b1, b2, b3;
                ldsm4t(b0, b1, b2, b3, bAddr + ks * (16 * BSTR) + g * 32);
                mma_h(acc[2 * g],     a0, a1, a2, a3, b0, b1);
                mma_h(acc[2 * g + 1], a0, a1, a2, a3, b2, b3);
            }
        }
        stage ^= 1;
    }

    // ---- epilogue ----
    int r1 = m0 + wm * 16 + (lane >> 2);
    int r2 = r1 + 8;
    float b1 = bias[r1], b2 = bias[r2];
#pragma unroll
    for (int g = 0; g < 8; ++g) {
        int col = n0 + wn * 64 + g * 8 + ((lane & 3) << 1);
        float2 w1 = make_float2(acc[g][0] + b1, acc[g][1] + b1);
        float2 w2 = make_float2(acc[g][2] + b2, acc[g][3] + b2);
        if (SPLITOUT) {
            __half* ChZ = Ch + (size_t)z * M * N;
            *(uint32_t*)(ChZ + (size_t)r1 * N + col) =
                pk_h2(__float2half_rn(w1.x), __float2half_rn(w1.y));
            *(uint32_t*)(ChZ + (size_t)r2 * N + col) =
                pk_h2(__float2half_rn(w2.x), __float2half_rn(w2.y));
        } else {
            float* Cz = C + (size_t)z * M * N;
            if (RES) {
                float2 q1 = *(const float2*)(res + (size_t)z * M * N + (size_t)r1 * N + col);
                float2 q2 = *(const float2*)(res + (size_t)z * M * N + (size_t)r2 * N + col);
                w1.x += q1.x; w1.y += q1.y;
                w2.x += q2.x; w2.y += q2.y;
            }
            *(float2*)(Cz + (size_t)r1 * N + col) = w1;
            *(float2*)(Cz + (size_t)r2 * N + col) = w2;
        }
    }
}

// ===================== attention: fp16 single =====================
#define BT2 128
#define BS2 64
#define NIT (T_LEN / BS2)
#define QSTR 272
#define KSTR 144
#define SM_Q   0
#define SM_KV  17408
#define KVS_K  0
#define KVS_V  9216
#define KVSTAGE 18432
#define ATTN_SMEM (SM_KV + 2 * KVSTAGE)   // 54272

__global__ void __launch_bounds__(256, 2) attn_mma()
{
    extern __shared__ char sm[];
    const int tid  = threadIdx.x;
    const int wid  = tid >> 5;
    const int lane = tid & 31;
    const int t0 = blockIdx.x * BT2;
    const int h  = blockIdx.y;
    const int b  = blockIdx.z;

    const size_t qoff = ((size_t)b * 3 * CC + h * HD) * T_LEN;
    const __half* qh = g_qh + qoff;
    const __half* kh = qh + (size_t)CC * T_LEN;
    const __half* vh = kh + (size_t)CC * T_LEN;

    const uint32_t smb = smem_u32(sm);
    const int kvd = tid >> 3, kvc = tid & 7;
    const int kvd2 = kvd + 32;
    auto kv_load = [&](int s0, int st) {
        uint32_t base = smb + SM_KV + (uint32_t)st * KVSTAGE;
        size_t g  = (size_t)kvd * T_LEN + s0 + kvc * 8;
        size_t g2 = (size_t)kvd2 * T_LEN + s0 + kvc * 8;
        uint32_t o  = base + kvd * KSTR + kvc * 16;
        uint32_t o2 = base + kvd2 * KSTR + kvc * 16;
        cp16(o + KVS_K,  kh + g);
        cp16(o + KVS_V,  vh + g);
        cp16(o2 + KVS_K, kh + g2);
        cp16(o2 + KVS_V, vh + g2);
    };

    kv_load(0, 0);
    CP_COMMIT();

    // Q tile [d=64][t=128] fp16, 16 chunks/row
#pragma unroll
    for (int l = 0; l < 4; ++l) {
        int f = tid + l * 256;
        int d = f >> 4;
        int c = f & 15;
        size_t g = (size_t)d * T_LEN + t0 + c * 8;
        *(uint4*)(sm + SM_Q + d * QSTR + c * 16) = *(const uint4*)(qh + g);
    }

    float oacc[32];
#pragma unroll
    for (int i = 0; i < 32; ++i) oacc[i] = 0.f;
    float m_r1 = -INFINITY, m_r2 = -INFINITY, l_r1 = 0.f, l_r2 = 0.f;

    const int q8 = lane & 7;
    const int qh2 = (lane >> 3) & 1;
    const int qd2 = lane >> 4;
    const uint32_t qa = smb + SM_Q + (uint32_t)(q8 + 8 * qd2) * QSTR + wid * 32 + qh2 * 16;
    const int lr = lane & 15, lc = lane >> 4;
    const uint32_t kb_rel = KVS_K + (uint32_t)lr * KSTR + lc * 16;
    const int v8 = lane & 7;
    const int vh2b = (lane >> 3) & 1;
    const int vd2 = lane >> 4;
    const uint32_t vb_rel = KVS_V + (uint32_t)(v8 + 8 * vd2) * KSTR + vh2b * 16;

    const float scale2 = 0.044194173824159216f * 1.4426950408889634f;  // 512^-.5 * log2e

    int stage = 0;
    for (int it = 0; it < NIT; ++it) {
        CP_WAIT0();
        __syncthreads();
        if (it + 1 < NIT) { kv_load((it + 1) * BS2, stage ^ 1); CP_COMMIT(); }

        const uint32_t kvb = smb + SM_KV + (uint32_t)stage * KVSTAGE;
        const uint32_t kb = kvb + kb_rel;
        const uint32_t vb = kvb + vb_rel;

        // ---- S = Q K^T ----
        float sacc[32];
#pragma unroll
        for (int i = 0; i < 32; ++i) sacc[i] = 0.f;
#pragma unroll
        for (int ks = 0; ks < 4; ++ks) {
            uint32_t a0, a1, a2, a3;
            ldsm4t(a0, a1, a2, a3, qa + ks * (16 * QSTR));
#pragma unroll
            for (int np = 0; np < 4; ++np) {
                uint32_t b0, b1, b2, b3;
                ldsm4t(b0, b1, b2, b3, kb + ks * (16 * KSTR) + np * 32);
                mma_h(&sacc[np * 8],     a0, a1, a2, a3, b0, b1);
                mma_h(&sacc[np * 8 + 4], a0, a1, a2, a3, b2, b3);
            }
        }

        // ---- softmax (exp2 domain) ----
#pragma unroll
        for (int i = 0; i < 32; ++i) sacc[i] *= scale2;
        float nm1 = -INFINITY, nm2 = -INFINITY;
#pragma unroll
        for (int j = 0; j < 8; ++j) {
            nm1 = fmaxf(nm1, fmaxf(sacc[4 * j],     sacc[4 * j + 1]));
            nm2 = fmaxf(nm2, fmaxf(sacc[4 * j + 2], sacc[4 * j + 3]));
        }
        nm1 = fmaxf(nm1, __shfl_xor_sync(0xffffffffu, nm1, 1));
        nm1 = fmaxf(nm1, __shfl_xor_sync(0xffffffffu, nm1, 2));
        nm2 = fmaxf(nm2, __shfl_xor_sync(0xffffffffu, nm2, 1));
        nm2 = fmaxf(nm2, __shfl_xor_sync(0xffffffffu, nm2, 2));
        const float mn1 = fmaxf(m_r1, nm1);
        const float mn2 = fmaxf(m_r2, nm2);
        const float a1 = exp2f(m_r1 - mn1);
        const float a2 = exp2f(m_r2 - mn2);
        float s1 = 0.f, s2 = 0.f;
#pragma unroll
        for (int j = 0; j < 8; ++j) {
            float e0 = exp2f(sacc[4 * j]     - mn1);
            float e1 = exp2f(sacc[4 * j + 1] - mn1);
            float e2 = exp2f(sacc[4 * j + 2] - mn2);
            float e3 = exp2f(sacc[4 * j + 3] - mn2);
            sacc[4 * j] = e0; sacc[4 * j + 1] = e1; sacc[4 * j + 2] = e2; sacc[4 * j + 3] = e3;
            s1 += e0 + e1;
            s2 += e2 + e3;
        }
        s1 += __shfl_xor_sync(0xffffffffu, s1, 1);
        s1 += __shfl_xor_sync(0xffffffffu, s1, 2);
        s2 += __shfl_xor_sync(0xffffffffu, s2, 1);
        s2 += __shfl_xor_sync(0xffffffffu, s2, 2);
        l_r1 = l_r1 * a1 + s1;
        l_r2 = l_r2 * a2 + s2;
        m_r1 = mn1;
        m_r2 = mn2;
#pragma unroll
        for (int j = 0; j < 8; ++j) {
            oacc[4 * j]     *= a1;
            oacc[4 * j + 1] *= a1;
            oacc[4 * j + 2] *= a2;
            oacc[4 * j + 3] *= a2;
        }

        // ---- O += P V^T ----
#pragma unroll
        for (int ks = 0; ks < 4; ++ks) {
            const float* sA = &sacc[8 * ks];
            uint32_t p0 = pk_h2(__float2half_rn(sA[0]), __float2half_rn(sA[1]));
            uint32_t p1 = pk_h2(__float2half_rn(sA[2]), __float2half_rn(sA[3]));
            uint32_t p2 = pk_h2(__float2half_rn(sA[4]), __float2half_rn(sA[5]));
            uint32_t p3 = pk_h2(__float2half_rn(sA[6]), __float2half_rn(sA[7]));
#pragma unroll
            for (int np = 0; np < 4; ++np) {
                uint32_t b0, b1, b2, b3;
                ldsm4(b0, b1, b2, b3, vb + np * (16 * KSTR) + ks * 32);
                mma_h(&oacc[np * 8],     p0, p1, p2, p3, b0, b1);
                mma_h(&oacc[np * 8 + 4], p0, p1, p2, p3, b2, b3);
            }
        }
        stage ^= 1;
    }

    __syncthreads();
    // ---- epilogue: normalize, stage [d][t] fp32, write fp16 ----
    {
        float* so = (float*)(sm + SM_KV);
        const float i1 = 1.f / l_r1;
        const float i2 = 1.f / l_r2;
        const int r  = lane >> 2;
        const int tw = wid * 16;
#pragma unroll
        for (int j = 0; j < 8; ++j) {
            int d0 = 8 * j + ((lane & 3) << 1);
            so[(size_t)d0 * 128 + tw + r]           = oacc[4 * j]     * i1;
            so[(size_t)(d0 + 1) * 128 + tw + r]     = oacc[4 * j + 1] * i1;
            so[(size_t)d0 * 128 + tw + r + 8]       = oacc[4 * j + 2] * i2;
            so[(size_t)(d0 + 1) * 128 + tw + r + 8] = oacc[4 * j + 3] * i2;
        }
        __syncthreads();
        const size_t obase = ((size_t)b * CC + h * HD) * T_LEN;
#pragma unroll
        for (int l = 0; l < 8; ++l) {
            int f  = tid + l * 256;
            int c  = f >> 5;
            int t4 = (f & 31) << 2;
            float4 v = *(float4*)&so[(size_t)c * 128 + t4];
            uint32_t a = pk_h2(__float2half_rn(v.x), __float2half_rn(v.y));
            uint32_t d = pk_h2(__float2half_rn(v.z), __float2half_rn(v.w));
            *(uint2*)(g_xh + obase + (size_t)c * T_LEN + t0 + t4) = make_uint2(a, d);
        }
    }
}

// ===================== launch =====================
extern "C" void kernel_launch(void* const* d_in, const int* in_sizes, int n_in,
                              void* d_out, int out_size)
{
    const float* x      = (const float*)d_in[0];
    const float* qkv_w  = (const float*)d_in[1];
    const float* qkv_b  = (const float*)d_in[2];
    const float* proj_w = (const float*)d_in[3];
    const float* proj_b = (const float*)d_in[4];
    float* out = (float*)d_out;

    __half *wh, *xh, *qh;
    cudaGetSymbolAddress((void**)&wh, g_wh);
    cudaGetSymbolAddress((void**)&xh, g_xh);
    cudaGetSymbolAddress((void**)&qh, g_qh);

    cudaFuncSetAttribute((const void*)attn_mma,
                         cudaFuncAttributeMaxDynamicSharedMemorySize, ATTN_SMEM);
    cudaFuncSetAttribute((const void*)gemm_h<false, true>,
                         cudaFuncAttributeMaxDynamicSharedMemorySize, GEMM_SMEM);
    cudaFuncSetAttribute((const void*)gemm_h<true, false>,
                         cudaFuncAttributeMaxDynamicSharedMemorySize, GEMM_SMEM);

    const int QW4 = (3 * CC * CC) / 4;
    const int PW4 = (CC * CC) / 4;
    const int X4  = (int)(X_ELEMS / 4);
    const int PW_OFF = 3 * CC * CC;

    conv_h<<<(QW4 + 255) / 256, 256>>>(qkv_w, wh, QW4);
    conv_h<<<(PW4 + 255) / 256, 256>>>(proj_w, wh + PW_OFF, PW4);
    conv_h<<<(X4 + 255) / 256, 256>>>(x, xh, X4);

    // 1) qkv = W_qkv @ x + b  -> fp16
    gemm_h<false, true><<<dim3(T_LEN / 128, (3 * CC) / 64, BATCH), 256, GEMM_SMEM>>>(
        wh, xh, qkv_b, nullptr, nullptr, qh, 3 * CC, T_LEN, CC);

    // 2) attention (writes fp16 into xh)
    attn_mma<<<dim3(T_LEN / BT2, NH, BATCH), 256, ATTN_SMEM>>>();

    // 3) out = x + W_proj @ att + b
    gemm_h<true, false><<<dim3(T_LEN / 128, CC / 64, BATCH), 256, GEMM_SMEM>>>(
        wh + PW_OFF, xh, proj_b, x, out, nullptr, CC, T_LEN, CC);
}

// round 13
// speedup vs baseline: 2.9947x; 1.0282x over previous
#include <cuda_runtime.h>
#include <cuda_fp16.h>
#include <math.h>
#include <stdint.h>

#define CC     512
#define T_LEN  2048
#define BATCH  4
#define NH     8
#define HD     64

#define W_ELEMS (3 * CC * CC + CC * CC)             // qkv_w then proj_w
#define X_ELEMS ((size_t)BATCH * CC * T_LEN)
#define QKV_ELEMS ((size_t)BATCH * 3 * CC * T_LEN)
__device__ __half g_wh[W_ELEMS];                    // weights fp16
__device__ __half g_xh[X_ELEMS];                    // x fp16, later attn-out fp16
__device__ __half g_qh[QKV_ELEMS];                  // qkv fp16

// ===================== helpers =====================
__device__ __forceinline__ uint32_t smem_u32(const void* p) {
    uint32_t a;
    asm("{ .reg .u64 t; cvta.to.shared.u64 t, %1; cvt.u32.u64 %0, t; }" : "=r"(a) : "l"(p));
    return a;
}
__device__ __forceinline__ uint32_t pk_h2(__half a, __half b) {
    __half2 t(a, b);
    return *reinterpret_cast<uint32_t*>(&t);
}
__device__ __forceinline__ void ldsm4(uint32_t& r0, uint32_t& r1, uint32_t& r2, uint32_t& r3,
                                      uint32_t addr) {
    asm volatile("ldmatrix.sync.aligned.m8n8.x4.shared.b16 {%0,%1,%2,%3}, [%4];"
                 : "=r"(r0), "=r"(r1), "=r"(r2), "=r"(r3) : "r"(addr));
}
__device__ __forceinline__ void ldsm4t(uint32_t& r0, uint32_t& r1, uint32_t& r2, uint32_t& r3,
                                       uint32_t addr) {
    asm volatile("ldmatrix.sync.aligned.m8n8.x4.trans.shared.b16 {%0,%1,%2,%3}, [%4];"
                 : "=r"(r0), "=r"(r1), "=r"(r2), "=r"(r3) : "r"(addr));
}
__device__ __forceinline__ void mma_h(float* c, uint32_t a0, uint32_t a1, uint32_t a2,
                                      uint32_t a3, uint32_t b0, uint32_t b1) {
    asm volatile(
        "mma.sync.aligned.m16n8k16.row.col.f32.f16.f16.f32 "
        "{%0,%1,%2,%3}, {%4,%5,%6,%7}, {%8,%9}, {%0,%1,%2,%3};"
        : "+f"(c[0]), "+f"(c[1]), "+f"(c[2]), "+f"(c[3])
        : "r"(a0), "r"(a1), "r"(a2), "r"(a3), "r"(b0), "r"(b1));
}
__device__ __forceinline__ void cp16(uint32_t dst, const void* src) {
    asm volatile("cp.async.cg.shared.global [%0], [%1], 16;" :: "r"(dst), "l"(src));
}
#define CP_COMMIT() asm volatile("cp.async.commit_group;" ::: "memory")
#define CP_WAIT0()  asm volatile("cp.async.wait_group 0;" ::: "memory")

// ===================== prep: fp32 -> fp16 =====================
__global__ void __launch_bounds__(256) conv_h(
    const float* __restrict__ src, __half* __restrict__ dst, int n4)
{
    int i = blockIdx.x * blockDim.x + threadIdx.x;
    if (i >= n4) return;
    float4 v = ((const float4*)src)[i];
    uint32_t a = pk_h2(__float2half_rn(v.x), __float2half_rn(v.y));
    uint32_t b = pk_h2(__float2half_rn(v.z), __float2half_rn(v.w));
    ((uint2*)dst)[i] = make_uint2(a, b);
}

// ===================== fp16 single GEMM =====================
// C[z][M,N] = A[M,K] * B[z][K,N], CTA 128m x 128n x 32k, 8 warps (4m x 2n),
// warp tile 32x64, cp.async 2-stage.
#define ASTR 80          // 32 fp16 + pad
#define BSTR 272         // 128 fp16 + pad
#define SA    0
#define SB    10240
#define GSTAGE 18944
#define GEMM_SMEM (2 * GSTAGE)

template<bool RES, bool SPLITOUT>
__global__ void __launch_bounds__(256, 2) gemm_h(
    const __half* __restrict__ A, const __half* __restrict__ B,
    const float* __restrict__ bias, const float* __restrict__ res,
    float* __restrict__ C, __half* __restrict__ Ch,
    int M, int N, int K)
{
    extern __shared__ char sm[];
    const int z  = blockIdx.z;
    const int n0 = blockIdx.x * 128;
    const int m0 = blockIdx.y * 128;
    const int tid  = threadIdx.x;
    const int wid  = tid >> 5;
    const int lane = tid & 31;
    const int wm = wid & 3;          // 4 m-warps x 32 rows
    const int wn = wid >> 2;         // 2 n-warps x 64 cols

    const __half* Bz = B + (size_t)z * K * N;

    float acc[2][8][4];
#pragma unroll
    for (int i = 0; i < 2; i++)
#pragma unroll
        for (int j = 0; j < 8; j++)
#pragma unroll
            for (int e = 0; e < 4; e++) acc[i][j][e] = 0.f;

    const uint32_t smb = smem_u32(sm);
    const int lr = lane & 15;
    const int lc = lane >> 4;
    const uint32_t aRel = SA + (uint32_t)(wm * 32 + lr) * ASTR + lc * 16;
    const uint32_t bRel = SB + (uint32_t)lr * BSTR + wn * 128 + lc * 16;

    // cp.async coords: A 128 rows x 4 chunks; B 32 rows x 16 chunks
    const int ar  = tid >> 2,         ac  = (tid & 3) << 3;
    const int ar2 = (tid + 256) >> 2, ac2 = ((tid + 256) & 3) << 3;
    const int bk  = tid >> 4,         bn  = (tid & 15) << 3;
    const int bk2 = bk + 16;

    const int KS = K >> 5;

    auto load_slab = [&](int k0, int st) {
        uint32_t base = smb + (uint32_t)st * GSTAGE;
        size_t ga  = (size_t)(m0 + ar)  * K + k0 + ac;
        size_t ga2 = (size_t)(m0 + ar2) * K + k0 + ac2;
        size_t gb  = (size_t)(k0 + bk)  * N + n0 + bn;
        size_t gb2 = (size_t)(k0 + bk2) * N + n0 + bn;
        cp16(base + SA + ar * ASTR + ac * 2,  A + ga);
        cp16(base + SA + ar2 * ASTR + ac2 * 2, A + ga2);
        cp16(base + SB + bk * BSTR + bn * 2,  Bz + gb);
        cp16(base + SB + bk2 * BSTR + bn * 2, Bz + gb2);
    };

    load_slab(0, 0);
    CP_COMMIT();

    int stage = 0;
    for (int it = 0; it < KS; ++it) {
        CP_WAIT0();
        __syncthreads();
        if (it + 1 < KS) { load_slab((it + 1) << 5, stage ^ 1); CP_COMMIT(); }

        const uint32_t aAddr = smb + (uint32_t)stage * GSTAGE + aRel;
        const uint32_t bAddr = smb + (uint32_t)stage * GSTAGE + bRel;
#pragma unroll
        for (int ks = 0; ks < 2; ++ks) {
            uint32_t b0[4], b1[4], b2[4], b3[4];
#pragma unroll
            for (int g = 0; g < 4; ++g)
                ldsm4t(b0[g], b1[g], b2[g], b3[g], bAddr + ks * (16 * BSTR) + g * 32);
#pragma unroll
            for (int mt = 0; mt < 2; ++mt) {
                uint32_t a0, a1, a2, a3;
                ldsm4(a0, a1, a2, a3, aAddr + mt * (16 * ASTR) + ks * 32);
#pragma unroll
                for (int g = 0; g < 4; ++g) {
                    mma_h(acc[mt][2 * g],     a0, a1, a2, a3, b0[g], b1[g]);
                    mma_h(acc[mt][2 * g + 1], a0, a1, a2, a3, b2[g], b3[g]);
                }
            }
        }
        stage ^= 1;
    }

    // ---- epilogue ----
#pragma unroll
    for (int mt = 0; mt < 2; ++mt) {
        int r1 = m0 + wm * 32 + mt * 16 + (lane >> 2);
        int r2 = r1 + 8;
        float b1 = bias[r1], b2 = bias[r2];
#pragma unroll
        for (int g = 0; g < 8; ++g) {
            int col = n0 + wn * 64 + g * 8 + ((lane & 3) << 1);
            float2 w1 = make_float2(acc[mt][g][0] + b1, acc[mt][g][1] + b1);
            float2 w2 = make_float2(acc[mt][g][2] + b2, acc[mt][g][3] + b2);
            if (SPLITOUT) {
                __half* ChZ = Ch + (size_t)z * M * N;
                *(uint32_t*)(ChZ + (size_t)r1 * N + col) =
                    pk_h2(__float2half_rn(w1.x), __float2half_rn(w1.y));
                *(uint32_t*)(ChZ + (size_t)r2 * N + col) =
                    pk_h2(__float2half_rn(w2.x), __float2half_rn(w2.y));
            } else {
                float* Cz = C + (size_t)z * M * N;
                if (RES) {
                    float2 q1 = *(const float2*)(res + (size_t)z * M * N + (size_t)r1 * N + col);
                    float2 q2 = *(const float2*)(res + (size_t)z * M * N + (size_t)r2 * N + col);
                    w1.x += q1.x; w1.y += q1.y;
                    w2.x += q2.x; w2.y += q2.y;
                }
                *(float2*)(Cz + (size_t)r1 * N + col) = w1;
                *(float2*)(Cz + (size_t)r2 * N + col) = w2;
            }
        }
    }
}

// ===================== attention: fp16 single (R12, verified) =====================
#define BT2 128
#define BS2 64
#define NIT (T_LEN / BS2)
#define QSTR 272
#define KSTR 144
#define SM_Q   0
#define SM_KV  17408
#define KVS_K  0
#define KVS_V  9216
#define KVSTAGE 18432
#define ATTN_SMEM (SM_KV + 2 * KVSTAGE)   // 54272

__global__ void __launch_bounds__(256, 2) attn_mma()
{
    extern __shared__ char sm[];
    const int tid  = threadIdx.x;
    const int wid  = tid >> 5;
    const int lane = tid & 31;
    const int t0 = blockIdx.x * BT2;
    const int h  = blockIdx.y;
    const int b  = blockIdx.z;

    const size_t qoff = ((size_t)b * 3 * CC + h * HD) * T_LEN;
    const __half* qh = g_qh + qoff;
    const __half* kh = qh + (size_t)CC * T_LEN;
    const __half* vh = kh + (size_t)CC * T_LEN;

    const uint32_t smb = smem_u32(sm);
    const int kvd = tid >> 3, kvc = tid & 7;
    const int kvd2 = kvd + 32;
    auto kv_load = [&](int s0, int st) {
        uint32_t base = smb + SM_KV + (uint32_t)st * KVSTAGE;
        size_t g  = (size_t)kvd * T_LEN + s0 + kvc * 8;
        size_t g2 = (size_t)kvd2 * T_LEN + s0 + kvc * 8;
        uint32_t o  = base + kvd * KSTR + kvc * 16;
        uint32_t o2 = base + kvd2 * KSTR + kvc * 16;
        cp16(o + KVS_K,  kh + g);
        cp16(o + KVS_V,  vh + g);
        cp16(o2 + KVS_K, kh + g2);
        cp16(o2 + KVS_V, vh + g2);
    };

    kv_load(0, 0);
    CP_COMMIT();

#pragma unroll
    for (int l = 0; l < 4; ++l) {
        int f = tid + l * 256;
        int d = f >> 4;
        int c = f & 15;
        size_t g = (size_t)d * T_LEN + t0 + c * 8;
        *(uint4*)(sm + SM_Q + d * QSTR + c * 16) = *(const uint4*)(qh + g);
    }

    float oacc[32];
#pragma unroll
    for (int i = 0; i < 32; ++i) oacc[i] = 0.f;
    float m_r1 = -INFINITY, m_r2 = -INFINITY, l_r1 = 0.f, l_r2 = 0.f;

    const int q8 = lane & 7;
    const int qh2 = (lane >> 3) & 1;
    const int qd2 = lane >> 4;
    const uint32_t qa = smb + SM_Q + (uint32_t)(q8 + 8 * qd2) * QSTR + wid * 32 + qh2 * 16;
    const int lr = lane & 15, lc = lane >> 4;
    const uint32_t kb_rel = KVS_K + (uint32_t)lr * KSTR + lc * 16;
    const int v8 = lane & 7;
    const int vh2b = (lane >> 3) & 1;
    const int vd2 = lane >> 4;
    const uint32_t vb_rel = KVS_V + (uint32_t)(v8 + 8 * vd2) * KSTR + vh2b * 16;

    const float scale2 = 0.044194173824159216f * 1.4426950408889634f;  // 512^-.5 * log2e

    int stage = 0;
    for (int it = 0; it < NIT; ++it) {
        CP_WAIT0();
        __syncthreads();
        if (it + 1 < NIT) { kv_load((it + 1) * BS2, stage ^ 1); CP_COMMIT(); }

        const uint32_t kvb = smb + SM_KV + (uint32_t)stage * KVSTAGE;
        const uint32_t kb = kvb + kb_rel;
        const uint32_t vb = kvb + vb_rel;

        // ---- S = Q K^T ----
        float sacc[32];
#pragma unroll
        for (int i = 0; i < 32; ++i) sacc[i] = 0.f;
#pragma unroll
        for (int ks = 0; ks < 4; ++ks) {
            uint32_t a0, a1, a2, a3;
            ldsm4t(a0, a1, a2, a3, qa + ks * (16 * QSTR));
#pragma unroll
            for (int np = 0; np < 4; ++np) {
                uint32_t b0, b1, b2, b3;
                ldsm4t(b0, b1, b2, b3, kb + ks * (16 * KSTR) + np * 32);
                mma_h(&sacc[np * 8],     a0, a1, a2, a3, b0, b1);
                mma_h(&sacc[np * 8 + 4], a0, a1, a2, a3, b2, b3);
            }
        }

        // ---- softmax (exp2 domain) ----
#pragma unroll
        for (int i = 0; i < 32; ++i) sacc[i] *= scale2;
        float nm1 = -INFINITY, nm2 = -INFINITY;
#pragma unroll
        for (int j = 0; j < 8; ++j) {
            nm1 = fmaxf(nm1, fmaxf(sacc[4 * j],     sacc[4 * j + 1]));
            nm2 = fmaxf(nm2, fmaxf(sacc[4 * j + 2], sacc[4 * j + 3]));
        }
        nm1 = fmaxf(nm1, __shfl_xor_sync(0xffffffffu, nm1, 1));
        nm1 = fmaxf(nm1, __shfl_xor_sync(0xffffffffu, nm1, 2));
        nm2 = fmaxf(nm2, __shfl_xor_sync(0xffffffffu, nm2, 1));
        nm2 = fmaxf(nm2, __shfl_xor_sync(0xffffffffu, nm2, 2));
        const float mn1 = fmaxf(m_r1, nm1);
        const float mn2 = fmaxf(m_r2, nm2);
        const float a1 = exp2f(m_r1 - mn1);
        const float a2 = exp2f(m_r2 - mn2);
        float s1 = 0.f, s2 = 0.f;
#pragma unroll
        for (int j = 0; j < 8; ++j) {
            float e0 = exp2f(sacc[4 * j]     - mn1);
            float e1 = exp2f(sacc[4 * j + 1] - mn1);
            float e2 = exp2f(sacc[4 * j + 2] - mn2);
            float e3 = exp2f(sacc[4 * j + 3] - mn2);
            sacc[4 * j] = e0; sacc[4 * j + 1] = e1; sacc[4 * j + 2] = e2; sacc[4 * j + 3] = e3;
            s1 += e0 + e1;
            s2 += e2 + e3;
        }
        s1 += __shfl_xor_sync(0xffffffffu, s1, 1);
        s1 += __shfl_xor_sync(0xffffffffu, s1, 2);
        s2 += __shfl_xor_sync(0xffffffffu, s2, 1);
        s2 += __shfl_xor_sync(0xffffffffu, s2, 2);
        l_r1 = l_r1 * a1 + s1;
        l_r2 = l_r2 * a2 + s2;
        m_r1 = mn1;
        m_r2 = mn2;
#pragma unroll
        for (int j = 0; j < 8; ++j) {
            oacc[4 * j]     *= a1;
            oacc[4 * j + 1] *= a1;
            oacc[4 * j + 2] *= a2;
            oacc[4 * j + 3] *= a2;
        }

        // ---- O += P V^T ----
#pragma unroll
        for (int ks = 0; ks < 4; ++ks) {
            const float* sA = &sacc[8 * ks];
            uint32_t p0 = pk_h2(__float2half_rn(sA[0]), __float2half_rn(sA[1]));
            uint32_t p1 = pk_h2(__float2half_rn(sA[2]), __float2half_rn(sA[3]));
            uint32_t p2 = pk_h2(__float2half_rn(sA[4]), __float2half_rn(sA[5]));
            uint32_t p3 = pk_h2(__float2half_rn(sA[6]), __float2half_rn(sA[7]));
#pragma unroll
            for (int np = 0; np < 4; ++np) {
                uint32_t b0, b1, b2, b3;
                ldsm4(b0, b1, b2, b3, vb + np * (16 * KSTR) + ks * 32);
                mma_h(&oacc[np * 8],     p0, p1, p2, p3, b0, b1);
                mma_h(&oacc[np * 8 + 4], p0, p1, p2, p3, b2, b3);
            }
        }
        stage ^= 1;
    }

    __syncthreads();
    // ---- epilogue: normalize, stage [d][t] fp32, write fp16 ----
    {
        float* so = (float*)(sm + SM_KV);
        const float i1 = 1.f / l_r1;
        const float i2 = 1.f / l_r2;
        const int r  = lane >> 2;
        const int tw = wid * 16;
#pragma unroll
        for (int j = 0; j < 8; ++j) {
            int d0 = 8 * j + ((lane & 3) << 1);
            so[(size_t)d0 * 128 + tw + r]           = oacc[4 * j]     * i1;
            so[(size_t)(d0 + 1) * 128 + tw + r]     = oacc[4 * j + 1] * i1;
            so[(size_t)d0 * 128 + tw + r + 8]       = oacc[4 * j + 2] * i2;
            so[(size_t)(d0 + 1) * 128 + tw + r + 8] = oacc[4 * j + 3] * i2;
        }
        __syncthreads();
        const size_t obase = ((size_t)b * CC + h * HD) * T_LEN;
#pragma unroll
        for (int l = 0; l < 8; ++l) {
            int f  = tid + l * 256;
            int c  = f >> 5;
            int t4 = (f & 31) << 2;
            float4 v = *(float4*)&so[(size_t)c * 128 + t4];
            uint32_t a = pk_h2(__float2half_rn(v.x), __float2half_rn(v.y));
            uint32_t d = pk_h2(__float2half_rn(v.z), __float2half_rn(v.w));
            *(uint2*)(g_xh + obase + (size_t)c * T_LEN + t0 + t4) = make_uint2(a, d);
        }
    }
}

// ===================== launch =====================
extern "C" void kernel_launch(void* const* d_in, const int* in_sizes, int n_in,
                              void* d_out, int out_size)
{
    const float* x      = (const float*)d_in[0];
    const float* qkv_w  = (const float*)d_in[1];
    const float* qkv_b  = (const float*)d_in[2];
    const float* proj_w = (const float*)d_in[3];
    const float* proj_b = (const float*)d_in[4];
    float* out = (float*)d_out;

    __half *wh, *xh, *qh;
    cudaGetSymbolAddress((void**)&wh, g_wh);
    cudaGetSymbolAddress((void**)&xh, g_xh);
    cudaGetSymbolAddress((void**)&qh, g_qh);

    cudaFuncSetAttribute((const void*)attn_mma,
                         cudaFuncAttributeMaxDynamicSharedMemorySize, ATTN_SMEM);
    cudaFuncSetAttribute((const void*)gemm_h<false, true>,
                         cudaFuncAttributeMaxDynamicSharedMemorySize, GEMM_SMEM);
    cudaFuncSetAttribute((const void*)gemm_h<true, false>,
                         cudaFuncAttributeMaxDynamicSharedMemorySize, GEMM_SMEM);

    const int QW4 = (3 * CC * CC) / 4;
    const int PW4 = (CC * CC) / 4;
    const int X4  = (int)(X_ELEMS / 4);
    const int PW_OFF = 3 * CC * CC;

    conv_h<<<(QW4 + 255) / 256, 256>>>(qkv_w, wh, QW4);
    conv_h<<<(PW4 + 255) / 256, 256>>>(proj_w, wh + PW_OFF, PW4);
    conv_h<<<(X4 + 255) / 256, 256>>>(x, xh, X4);

    // 1) qkv = W_qkv @ x + b  -> fp16
    gemm_h<false, true><<<dim3(T_LEN / 128, (3 * CC) / 128, BATCH), 256, GEMM_SMEM>>>(
        wh, xh, qkv_b, nullptr, nullptr, qh, 3 * CC, T_LEN, CC);

    // 2) attention (writes fp16 into xh)
    attn_mma<<<dim3(T_LEN / BT2, NH, BATCH), 256, ATTN_SMEM>>>();

    // 3) out = x + W_proj @ att + b
    gemm_h<true, false><<<dim3(T_LEN / 128, CC / 128, BATCH), 256, GEMM_SMEM>>>(
        wh + PW_OFF, xh, proj_b, x, out, nullptr, CC, T_LEN, CC);
}

// round 14
// speedup vs baseline: 3.0877x; 1.0311x over previous
#include <cuda_runtime.h>
#include <cuda_fp16.h>
#include <math.h>
#include <stdint.h>

#define CC     512
#define T_LEN  2048
#define BATCH  4
#define NH     8
#define HD     64

#define W_ELEMS (3 * CC * CC + CC * CC)             // qkv_w then proj_w
#define X_ELEMS ((size_t)BATCH * CC * T_LEN)
#define QKV_ELEMS ((size_t)BATCH * 3 * CC * T_LEN)
__device__ __half g_wh[W_ELEMS];                    // weights fp16
__device__ __half g_xh[X_ELEMS];                    // x fp16, later attn-out fp16
__device__ __half g_qh[QKV_ELEMS];                  // qkv fp16

// ===================== helpers =====================
__device__ __forceinline__ uint32_t smem_u32(const void* p) {
    uint32_t a;
    asm("{ .reg .u64 t; cvta.to.shared.u64 t, %1; cvt.u32.u64 %0, t; }" : "=r"(a) : "l"(p));
    return a;
}
__device__ __forceinline__ uint32_t pk_h2(__half a, __half b) {
    __half2 t(a, b);
    return *reinterpret_cast<uint32_t*>(&t);
}
__device__ __forceinline__ void ldsm4(uint32_t& r0, uint32_t& r1, uint32_t& r2, uint32_t& r3,
                                      uint32_t addr) {
    asm volatile("ldmatrix.sync.aligned.m8n8.x4.shared.b16 {%0,%1,%2,%3}, [%4];"
                 : "=r"(r0), "=r"(r1), "=r"(r2), "=r"(r3) : "r"(addr));
}
__device__ __forceinline__ void ldsm4t(uint32_t& r0, uint32_t& r1, uint32_t& r2, uint32_t& r3,
                                       uint32_t addr) {
    asm volatile("ldmatrix.sync.aligned.m8n8.x4.trans.shared.b16 {%0,%1,%2,%3}, [%4];"
                 : "=r"(r0), "=r"(r1), "=r"(r2), "=r"(r3) : "r"(addr));
}
__device__ __forceinline__ void mma_h(float* c, uint32_t a0, uint32_t a1, uint32_t a2,
                                      uint32_t a3, uint32_t b0, uint32_t b1) {
    asm volatile(
        "mma.sync.aligned.m16n8k16.row.col.f32.f16.f16.f32 "
        "{%0,%1,%2,%3}, {%4,%5,%6,%7}, {%8,%9}, {%0,%1,%2,%3};"
        : "+f"(c[0]), "+f"(c[1]), "+f"(c[2]), "+f"(c[3])
        : "r"(a0), "r"(a1), "r"(a2), "r"(a3), "r"(b0), "r"(b1));
}
__device__ __forceinline__ void cp16(uint32_t dst, const void* src) {
    asm volatile("cp.async.cg.shared.global [%0], [%1], 16;" :: "r"(dst), "l"(src));
}
#define CP_COMMIT() asm volatile("cp.async.commit_group;" ::: "memory")
#define CP_WAIT1()  asm volatile("cp.async.wait_group 1;" ::: "memory")

// ===================== prep: fp32 -> fp16 =====================
__global__ void __launch_bounds__(256) conv_h(
    const float* __restrict__ src, __half* __restrict__ dst, int n4)
{
    int i = blockIdx.x * blockDim.x + threadIdx.x;
    if (i >= n4) return;
    float4 v = ((const float4*)src)[i];
    uint32_t a = pk_h2(__float2half_rn(v.x), __float2half_rn(v.y));
    uint32_t b = pk_h2(__float2half_rn(v.z), __float2half_rn(v.w));
    ((uint2*)dst)[i] = make_uint2(a, b);
}

// ===================== fp16 single GEMM =====================
// CTA 128m x 128n x 64k-slab, 8 warps (4m x 2n), warp tile 32x64, 3-stage cp.async
#define ASTR 144         // 64 fp16 + pad (9 granules)
#define BSTR 272         // 128 fp16 + pad (17 granules)
#define SA    0
#define SB    18432
#define GSTAGE 35840
#define GEMM_SMEM (3 * GSTAGE)

template<bool RES, bool SPLITOUT>
__global__ void __launch_bounds__(256, 2) gemm_h(
    const __half* __restrict__ A, const __half* __restrict__ B,
    const float* __restrict__ bias, const float* __restrict__ res,
    float* __restrict__ C, __half* __restrict__ Ch,
    int M, int N, int K)
{
    extern __shared__ char sm[];
    const int z  = blockIdx.z;
    const int n0 = blockIdx.x * 128;
    const int m0 = blockIdx.y * 128;
    const int tid  = threadIdx.x;
    const int wid  = tid >> 5;
    const int lane = tid & 31;
    const int wm = wid & 3;
    const int wn = wid >> 2;

    const __half* Bz = B + (size_t)z * K * N;

    float acc[2][8][4];
#pragma unroll
    for (int i = 0; i < 2; i++)
#pragma unroll
        for (int j = 0; j < 8; j++)
#pragma unroll
            for (int e = 0; e < 4; e++) acc[i][j][e] = 0.f;

    const uint32_t smb = smem_u32(sm);
    const int lr = lane & 15;
    const int lc = lane >> 4;
    const uint32_t aRel = SA + (uint32_t)(wm * 32 + lr) * ASTR + lc * 16;
    const uint32_t bRel = SB + (uint32_t)lr * BSTR + wn * 128 + lc * 16;

    // cp.async coords: A 128 rows x 8 chunks; B 64 rows x 16 chunks (4 each/thread)
    const int KS = K >> 6;   // 64-k slabs

    auto load_slab = [&](int k0, int st) {
        uint32_t base = smb + (uint32_t)st * GSTAGE;
#pragma unroll
        for (int l = 0; l < 4; ++l) {
            int f = tid + l * 256;
            int arow = f >> 3, achk = f & 7;
            int brow = f >> 4, bchk = f & 15;
            cp16(base + SA + arow * ASTR + achk * 16,
                 A + (size_t)(m0 + arow) * K + k0 + achk * 8);
            cp16(base + SB + brow * BSTR + bchk * 16,
                 Bz + (size_t)(k0 + brow) * N + n0 + bchk * 8);
        }
    };

    load_slab(0, 0);
    CP_COMMIT();
    load_slab(64, 1);
    CP_COMMIT();

    for (int it = 0; it < KS; ++it) {
        CP_WAIT1();
        __syncthreads();
        if (it + 2 < KS) load_slab((it + 2) << 6, (it + 2) % 3);
        CP_COMMIT();

        const uint32_t stb = (uint32_t)(it % 3) * GSTAGE;
        const uint32_t aAddr = smb + stb + aRel;
        const uint32_t bAddr = smb + stb + bRel;
#pragma unroll
        for (int ks = 0; ks < 4; ++ks) {
            uint32_t b0[4], b1[4], b2[4], b3[4];
#pragma unroll
            for (int g = 0; g < 4; ++g)
                ldsm4t(b0[g], b1[g], b2[g], b3[g], bAddr + ks * (16 * BSTR) + g * 32);
#pragma unroll
            for (int mt = 0; mt < 2; ++mt) {
                uint32_t a0, a1, a2, a3;
                ldsm4(a0, a1, a2, a3, aAddr + mt * (16 * ASTR) + ks * 32);
#pragma unroll
                for (int g = 0; g < 4; ++g) {
                    mma_h(acc[mt][2 * g],     a0, a1, a2, a3, b0[g], b1[g]);
                    mma_h(acc[mt][2 * g + 1], a0, a1, a2, a3, b2[g], b3[g]);
                }
            }
        }
    }

    // ---- epilogue ----
#pragma unroll
    for (int mt = 0; mt < 2; ++mt) {
        int r1 = m0 + wm * 32 + mt * 16 + (lane >> 2);
        int r2 = r1 + 8;
        float b1 = bias[r1], b2 = bias[r2];
#pragma unroll
        for (int g = 0; g < 8; ++g) {
            int col = n0 + wn * 64 + g * 8 + ((lane & 3) << 1);
            float2 w1 = make_float2(acc[mt][g][0] + b1, acc[mt][g][1] + b1);
            float2 w2 = make_float2(acc[mt][g][2] + b2, acc[mt][g][3] + b2);
            if (SPLITOUT) {
                __half* ChZ = Ch + (size_t)z * M * N;
                *(uint32_t*)(ChZ + (size_t)r1 * N + col) =
                    pk_h2(__float2half_rn(w1.x), __float2half_rn(w1.y));
                *(uint32_t*)(ChZ + (size_t)r2 * N + col) =
                    pk_h2(__float2half_rn(w2.x), __float2half_rn(w2.y));
            } else {
                float* Cz = C + (size_t)z * M * N;
                if (RES) {
                    float2 q1 = *(const float2*)(res + (size_t)z * M * N + (size_t)r1 * N + col);
                    float2 q2 = *(const float2*)(res + (size_t)z * M * N + (size_t)r2 * N + col);
                    w1.x += q1.x; w1.y += q1.y;
                    w2.x += q2.x; w2.y += q2.y;
                }
                *(float2*)(Cz + (size_t)r1 * N + col) = w1;
                *(float2*)(Cz + (size_t)r2 * N + col) = w2;
            }
        }
    }
}

// ===================== attention: fp16 single, 3-stage KV pipeline =====================
#define BT2 128
#define BS2 64
#define NIT (T_LEN / BS2)
#define QSTR 272
#define KSTR 144
#define SM_Q   0
#define SM_KV  17408
#define KVS_K  0
#define KVS_V  9216
#define KVSTAGE 18432
#define ATTN_SMEM (SM_KV + 3 * KVSTAGE)   // 72704

__global__ void __launch_bounds__(256, 2) attn_mma()
{
    extern __shared__ char sm[];
    const int tid  = threadIdx.x;
    const int wid  = tid >> 5;
    const int lane = tid & 31;
    const int t0 = blockIdx.x * BT2;
    const int h  = blockIdx.y;
    const int b  = blockIdx.z;

    const size_t qoff = ((size_t)b * 3 * CC + h * HD) * T_LEN;
    const __half* qh = g_qh + qoff;
    const __half* kh = qh + (size_t)CC * T_LEN;
    const __half* vh = kh + (size_t)CC * T_LEN;

    const uint32_t smb = smem_u32(sm);
    const int kvd = tid >> 3, kvc = tid & 7;
    const int kvd2 = kvd + 32;
    auto kv_load = [&](int s0, int st) {
        uint32_t base = smb + SM_KV + (uint32_t)st * KVSTAGE;
        size_t g  = (size_t)kvd * T_LEN + s0 + kvc * 8;
        size_t g2 = (size_t)kvd2 * T_LEN + s0 + kvc * 8;
        uint32_t o  = base + kvd * KSTR + kvc * 16;
        uint32_t o2 = base + kvd2 * KSTR + kvc * 16;
        cp16(o + KVS_K,  kh + g);
        cp16(o + KVS_V,  vh + g);
        cp16(o2 + KVS_K, kh + g2);
        cp16(o2 + KVS_V, vh + g2);
    };

    kv_load(0, 0);
    CP_COMMIT();

    // Q tile [d=64][t=128] (overlaps first KV loads)
#pragma unroll
    for (int l = 0; l < 4; ++l) {
        int f = tid + l * 256;
        int d = f >> 4;
        int c = f & 15;
        size_t g = (size_t)d * T_LEN + t0 + c * 8;
        *(uint4*)(sm + SM_Q + d * QSTR + c * 16) = *(const uint4*)(qh + g);
    }

    kv_load(BS2, 1);
    CP_COMMIT();

    float oacc[32];
#pragma unroll
    for (int i = 0; i < 32; ++i) oacc[i] = 0.f;
    float m_r1 = -INFINITY, m_r2 = -INFINITY, l_r1 = 0.f, l_r2 = 0.f;

    const int q8 = lane & 7;
    const int qh2 = (lane >> 3) & 1;
    const int qd2 = lane >> 4;
    const uint32_t qa = smb + SM_Q + (uint32_t)(q8 + 8 * qd2) * QSTR + wid * 32 + qh2 * 16;
    const int lr = lane & 15, lc = lane >> 4;
    const uint32_t kb_rel = KVS_K + (uint32_t)lr * KSTR + lc * 16;
    const int v8 = lane & 7;
    const int vh2b = (lane >> 3) & 1;
    const int vd2 = lane >> 4;
    const uint32_t vb_rel = KVS_V + (uint32_t)(v8 + 8 * vd2) * KSTR + vh2b * 16;

    const float scale2 = 0.044194173824159216f * 1.4426950408889634f;  // 512^-.5 * log2e

    for (int it = 0; it < NIT; ++it) {
        CP_WAIT1();
        __syncthreads();
        if (it + 2 < NIT) kv_load((it + 2) * BS2, (it + 2) % 3);
        CP_COMMIT();

        const uint32_t kvb = smb + SM_KV + (uint32_t)(it % 3) * KVSTAGE;
        const uint32_t kb = kvb + kb_rel;
        const uint32_t vb = kvb + vb_rel;

        // ---- S = Q K^T ----
        float sacc[32];
#pragma unroll
        for (int i = 0; i < 32; ++i) sacc[i] = 0.f;
#pragma unroll
        for (int ks = 0; ks < 4; ++ks) {
            uint32_t a0, a1, a2, a3;
            ldsm4t(a0, a1, a2, a3, qa + ks * (16 * QSTR));
#pragma unroll
            for (int np = 0; np < 4; ++np) {
                uint32_t b0, b1, b2, b3;
                ldsm4t(b0, b1, b2, b3, kb + ks * (16 * KSTR) + np * 32);
                mma_h(&sacc[np * 8],     a0, a1, a2, a3, b0, b1);
                mma_h(&sacc[np * 8 + 4], a0, a1, a2, a3, b2, b3);
            }
        }

        // ---- softmax (exp2 domain) ----
#pragma unroll
        for (int i = 0; i < 32; ++i) sacc[i] *= scale2;
        float nm1 = -INFINITY, nm2 = -INFINITY;
#pragma unroll
        for (int j = 0; j < 8; ++j) {
            nm1 = fmaxf(nm1, fmaxf(sacc[4 * j],     sacc[4 * j + 1]));
            nm2 = fmaxf(nm2, fmaxf(sacc[4 * j + 2], sacc[4 * j + 3]));
        }
        nm1 = fmaxf(nm1, __shfl_xor_sync(0xffffffffu, nm1, 1));
        nm1 = fmaxf(nm1, __shfl_xor_sync(0xffffffffu, nm1, 2));
        nm2 = fmaxf(nm2, __shfl_xor_sync(0xffffffffu, nm2, 1));
        nm2 = fmaxf(nm2, __shfl_xor_sync(0xffffffffu, nm2, 2));
        const float mn1 = fmaxf(m_r1, nm1);
        const float mn2 = fmaxf(m_r2, nm2);
        const float a1 = exp2f(m_r1 - mn1);
        const float a2 = exp2f(m_r2 - mn2);
        float s1 = 0.f, s2 = 0.f;
#pragma unroll
        for (int j = 0; j < 8; ++j) {
            float e0 = exp2f(sacc[4 * j]     - mn1);
            float e1 = exp2f(sacc[4 * j + 1] - mn1);
            float e2 = exp2f(sacc[4 * j + 2] - mn2);
            float e3 = exp2f(sacc[4 * j + 3] - mn2);
            sacc[4 * j] = e0; sacc[4 * j + 1] = e1; sacc[4 * j + 2] = e2; sacc[4 * j + 3] = e3;
            s1 += e0 + e1;
            s2 += e2 + e3;
        }
        s1 += __shfl_xor_sync(0xffffffffu, s1, 1);
        s1 += __shfl_xor_sync(0xffffffffu, s1, 2);
        s2 += __shfl_xor_sync(0xffffffffu, s2, 1);
        s2 += __shfl_xor_sync(0xffffffffu, s2, 2);
        l_r1 = l_r1 * a1 + s1;
        l_r2 = l_r2 * a2 + s2;
        m_r1 = mn1;
        m_r2 = mn2;
#pragma unroll
        for (int j = 0; j < 8; ++j) {
            oacc[4 * j]     *= a1;
            oacc[4 * j + 1] *= a1;
            oacc[4 * j + 2] *= a2;
            oacc[4 * j + 3] *= a2;
        }

        // ---- O += P V^T ----
#pragma unroll
        for (int ks = 0; ks < 4; ++ks) {
            const float* sA = &sacc[8 * ks];
            uint32_t p0 = pk_h2(__float2half_rn(sA[0]), __float2half_rn(sA[1]));
            uint32_t p1 = pk_h2(__float2half_rn(sA[2]), __float2half_rn(sA[3]));
            uint32_t p2 = pk_h2(__float2half_rn(sA[4]), __float2half_rn(sA[5]));
            uint32_t p3 = pk_h2(__float2half_rn(sA[6]), __float2half_rn(sA[7]));
#pragma unroll
            for (int np = 0; np < 4; ++np) {
                uint32_t b0, b1, b2, b3;
                ldsm4(b0, b1, b2, b3, vb + np * (16 * KSTR) + ks * 32);
                mma_h(&oacc[np * 8],     p0, p1, p2, p3, b0, b1);
                mma_h(&oacc[np * 8 + 4], p0, p1, p2, p3, b2, b3);
            }
        }
    }

    __syncthreads();
    // ---- epilogue: normalize, stage [d][t] fp32, write fp16 ----
    {
        float* so = (float*)(sm + SM_KV);
        const float i1 = 1.f / l_r1;
        const float i2 = 1.f / l_r2;
        const int r  = lane >> 2;
        const int tw = wid * 16;
#pragma unroll
        for (int j = 0; j < 8; ++j) {
            int d0 = 8 * j + ((lane & 3) << 1);
            so[(size_t)d0 * 128 + tw + r]           = oacc[4 * j]     * i1;
            so[(size_t)(d0 + 1) * 128 + tw + r]     = oacc[4 * j + 1] * i1;
            so[(size_t)d0 * 128 + tw + r + 8]       = oacc[4 * j + 2] * i2;
            so[(size_t)(d0 + 1) * 128 + tw + r + 8] = oacc[4 * j + 3] * i2;
        }
        __syncthreads();
        const size_t obase = ((size_t)b * CC + h * HD) * T_LEN;
#pragma unroll
        for (int l = 0; l < 8; ++l) {
            int f  = tid + l * 256;
            int c  = f >> 5;
            int t4 = (f & 31) << 2;
            float4 v = *(float4*)&so[(size_t)c * 128 + t4];
            uint32_t a = pk_h2(__float2half_rn(v.x), __float2half_rn(v.y));
            uint32_t d = pk_h2(__float2half_rn(v.z), __float2half_rn(v.w));
            *(uint2*)(g_xh + obase + (size_t)c * T_LEN + t0 + t4) = make_uint2(a, d);
        }
    }
}

// ===================== launch =====================
extern "C" void kernel_launch(void* const* d_in, const int* in_sizes, int n_in,
                              void* d_out, int out_size)
{
    const float* x      = (const float*)d_in[0];
    const float* qkv_w  = (const float*)d_in[1];
    const float* qkv_b  = (const float*)d_in[2];
    const float* proj_w = (const float*)d_in[3];
    const float* proj_b = (const float*)d_in[4];
    float* out = (float*)d_out;

    __half *wh, *xh, *qh;
    cudaGetSymbolAddress((void**)&wh, g_wh);
    cudaGetSymbolAddress((void**)&xh, g_xh);
    cudaGetSymbolAddress((void**)&qh, g_qh);

    cudaFuncSetAttribute((const void*)attn_mma,
                         cudaFuncAttributeMaxDynamicSharedMemorySize, ATTN_SMEM);
    cudaFuncSetAttribute((const void*)gemm_h<false, true>,
                         cudaFuncAttributeMaxDynamicSharedMemorySize, GEMM_SMEM);
    cudaFuncSetAttribute((const void*)gemm_h<true, false>,
                         cudaFuncAttributeMaxDynamicSharedMemorySize, GEMM_SMEM);

    const int QW4 = (3 * CC * CC) / 4;
    const int PW4 = (CC * CC) / 4;
    const int X4  = (int)(X_ELEMS / 4);
    const int PW_OFF = 3 * CC * CC;

    conv_h<<<(QW4 + 255) / 256, 256>>>(qkv_w, wh, QW4);
    conv_h<<<(PW4 + 255) / 256, 256>>>(proj_w, wh + PW_OFF, PW4);
    conv_h<<<(X4 + 255) / 256, 256>>>(x, xh, X4);

    // 1) qkv = W_qkv @ x + b  -> fp16
    gemm_h<false, true><<<dim3(T_LEN / 128, (3 * CC) / 128, BATCH), 256, GEMM_SMEM>>>(
        wh, xh, qkv_b, nullptr, nullptr, qh, 3 * CC, T_LEN, CC);

    // 2) attention (writes fp16 into xh)
    attn_mma<<<dim3(T_LEN / BT2, NH, BATCH), 256, ATTN_SMEM>>>();

    // 3) out = x + W_proj @ att + b
    gemm_h<true, false><<<dim3(T_LEN / 128, CC / 128, BATCH), 256, GEMM_SMEM>>>(
        wh + PW_OFF, xh, proj_b, x, out, nullptr, CC, T_LEN, CC);
}